// round 1
// baseline (speedup 1.0000x reference)
#include <cuda_runtime.h>

// Problem constants (shapes fixed by the dataset)
#define NMAX 100000
#define EMAX 1600000

// ---------------- scratch (device globals; no allocation allowed) ----------
__device__ float g_y1[NMAX * 64];
__device__ float g_y2[NMAX * 64];
__device__ float g_y3[NMAX * 64];
__device__ float g_y4[NMAX * 64];
__device__ float g_xl[NMAX * 64];
__device__ float g_xh[NMAX * 64];
__device__ float2 g_D1[NMAX];   // {dl, dh}
__device__ float2 g_D2[NMAX];   // {dll, dhh}
__device__ int    g_cnt[NMAX];
__device__ int    g_s[NMAX];

// ---------------- zero scratch each replay ---------------------------------
__global__ void k_zero(int n) {
    int stride = gridDim.x * blockDim.x;
    int i0 = blockIdx.x * blockDim.x + threadIdx.x;
    int nv = n * 16;  // n*64 floats = n*16 float4
    float4 z = make_float4(0.f, 0.f, 0.f, 0.f);
    float4* y1 = (float4*)g_y1;
    float4* y2 = (float4*)g_y2;
    float4* y3 = (float4*)g_y3;
    float4* y4 = (float4*)g_y4;
    for (int i = i0; i < nv; i += stride) {
        y1[i] = z; y2[i] = z; y3[i] = z; y4[i] = z;
    }
    for (int i = i0; i < n; i += stride) { g_cnt[i] = 0; g_s[i] = 0; }
}

// ---------------- degree pass: cnt[r] += 1, s[r] += cc[c] (skip self) ------
__global__ void k_deg(const int* __restrict__ col, const int* __restrict__ row,
                      const int* __restrict__ cc, int E) {
    int e = blockIdx.x * blockDim.x + threadIdx.x;
    if (e >= E) return;
    int r = __ldg(row + e);
    int c = __ldg(col + e);
    if (r == c) return;
    atomicAdd(&g_cnt[r], 1);
    atomicAdd(&g_s[r], __ldg(cc + c));
}

// ---------------- normalization coefficients -------------------------------
__global__ void k_coef(const int* __restrict__ cc, int n) {
    int i = blockIdx.x * blockDim.x + threadIdx.x;
    if (i >= n) return;
    float cnt = (float)g_cnt[i];
    float sv  = (float)g_s[i];
    int cci = __ldg(cc + i);
    // deg = masked non-self edge sum + 1 (filled diagonal) -> always > 0
    float dl  = rsqrtf((cci ? cnt : 0.f) + 1.f);
    float dh  = rsqrtf((cci ? 0.f : cnt) + 1.f);
    float dll = rsqrtf(sv + 1.f);
    float dhh = rsqrtf(cnt - sv + 1.f);
    g_D1[i] = make_float2(dl, dh);
    g_D2[i] = make_float2(dll, dhh);
}

// ---------------- fused dual-channel SpMM (16 lanes per edge) --------------
// PASS 0: select on cc[row]; src = x for both; dst = y1 (cc) / y3 (rev); D1
// PASS 1: select on cc[col]; src = xl/xh;     dst = y2 (cc) / y4 (rev); D2
template <int PASS>
__global__ void __launch_bounds__(256) k_spmm(const int* __restrict__ col,
                                              const int* __restrict__ row,
                                              const int* __restrict__ cc,
                                              const float* __restrict__ x,
                                              int E) {
    int t = blockIdx.x * blockDim.x + threadIdx.x;
    int e = t >> 4;
    if (e >= E) return;
    int p = t & 15;
    int r = __ldg(row + e);
    int c = __ldg(col + e);
    if (r == c) return;

    const float2* D = (PASS == 0) ? g_D1 : g_D2;
    int sel = __ldg(cc + ((PASS == 0) ? r : c));
    float2 dr = __ldg(D + r);
    float2 dc = __ldg(D + c);

    float w;
    const float* src;
    float* dst;
    if (sel) {
        w = dr.x * dc.x;
        src = (PASS == 0) ? x : g_xl;
        dst = (PASS == 0) ? g_y1 : g_y2;
    } else {
        w = dr.y * dc.y;
        src = (PASS == 0) ? x : g_xh;
        dst = (PASS == 0) ? g_y3 : g_y4;
    }

    float4 v = __ldg((const float4*)(src + c * 64) + p);
    v.x *= w; v.y *= w; v.z *= w; v.w *= w;
    atomicAdd((float4*)(dst + r * 64) + p, v);  // lowers to RED.128 (sm_90+)
}

// ---------------- dense layer 1: xl/xh = relu(sage(...)) -------------------
// warp per node; W1l,W1r,W3l,W3r staged in shared (64 KB dynamic)
__global__ void __launch_bounds__(256) k_dense1(const float* __restrict__ x,
                                                const float* __restrict__ W1l,
                                                const float* __restrict__ W1r,
                                                const float* __restrict__ W3l,
                                                const float* __restrict__ W3r,
                                                int n) {
    extern __shared__ float s[];
    float* s1l = s;
    float* s1r = s + 4096;
    float* s3l = s + 8192;
    float* s3r = s + 12288;
    int tid = threadIdx.x;
    {
        float4* d4 = (float4*)s;
        for (int i = tid; i < 4096; i += 256) {
            const float* srcm = (i < 1024) ? W1l : (i < 2048) ? W1r : (i < 3072) ? W3l : W3r;
            d4[i] = ((const float4*)srcm)[i & 1023];
        }
    }
    __syncthreads();

    int warp = tid >> 5, l = tid & 31;
    int node = blockIdx.x * 8 + warp;
    if (node >= n) return;

    int base = node * 64;
    float xv0 = x[base + l], xv1 = x[base + l + 32];
    float2 d = g_D1[node];
    float dl2 = d.x * d.x, dh2 = d.y * d.y;
    float a10 = g_y1[base + l] + dl2 * xv0, a11 = g_y1[base + l + 32] + dl2 * xv1;
    float a30 = g_y3[base + l] + dh2 * xv0, a31 = g_y3[base + l + 32] + dh2 * xv1;

    float l0 = 0.f, l1 = 0.f, h0 = 0.f, h1 = 0.f;
    const unsigned m = 0xffffffffu;
#pragma unroll
    for (int k = 0; k < 32; k++) {
        float bx = __shfl_sync(m, xv0, k);
        float b1 = __shfl_sync(m, a10, k);
        float b3 = __shfl_sync(m, a30, k);
        int o = k * 64;
        l0 += b1 * s1l[o + l]      + bx * s1r[o + l];
        l1 += b1 * s1l[o + l + 32] + bx * s1r[o + l + 32];
        h0 += b3 * s3l[o + l]      + bx * s3r[o + l];
        h1 += b3 * s3l[o + l + 32] + bx * s3r[o + l + 32];
    }
#pragma unroll
    for (int k = 0; k < 32; k++) {
        float bx = __shfl_sync(m, xv1, k);
        float b1 = __shfl_sync(m, a11, k);
        float b3 = __shfl_sync(m, a31, k);
        int o = (k + 32) * 64;
        l0 += b1 * s1l[o + l]      + bx * s1r[o + l];
        l1 += b1 * s1l[o + l + 32] + bx * s1r[o + l + 32];
        h0 += b3 * s3l[o + l]      + bx * s3r[o + l];
        h1 += b3 * s3l[o + l + 32] + bx * s3r[o + l + 32];
    }
    g_xl[base + l]      = fmaxf(l0, 0.f);
    g_xl[base + l + 32] = fmaxf(l1, 0.f);
    g_xh[base + l]      = fmaxf(h0, 0.f);
    g_xh[base + l + 32] = fmaxf(h1, 0.f);
}

// ---------------- dense layer 2 + mix + classifier -------------------------
// shared: W2l W2r W4l W4r WX (20480) + linW (2560) + linb (40) + stage (512)
__global__ void __launch_bounds__(256) k_dense2(const float* __restrict__ x,
                                                const int* __restrict__ cc,
                                                const float* __restrict__ W2l,
                                                const float* __restrict__ W2r,
                                                const float* __restrict__ W4l,
                                                const float* __restrict__ W4r,
                                                const float* __restrict__ WX,
                                                const float* __restrict__ lam1,
                                                const float* __restrict__ lam2,
                                                const float* __restrict__ linW,
                                                const float* __restrict__ linB,
                                                float* __restrict__ out, int n) {
    extern __shared__ float s[];
    float* s2l = s;
    float* s2r = s + 4096;
    float* s4l = s + 8192;
    float* s4r = s + 12288;
    float* sx  = s + 16384;
    float* slin  = s + 20480;   // 2560
    float* slinb = s + 23040;   // 40
    float* sstg  = s + 23080;   // 8 warps * 64

    int tid = threadIdx.x;
    {
        float4* d4 = (float4*)s;
        for (int i = tid; i < 5120; i += 256) {
            const float* srcm = (i < 1024) ? W2l : (i < 2048) ? W2r :
                                (i < 3072) ? W4l : (i < 4096) ? W4r : WX;
            d4[i] = ((const float4*)srcm)[i & 1023];
        }
        float4* l4 = (float4*)slin;
        for (int i = tid; i < 640; i += 256) l4[i] = ((const float4*)linW)[i];
        if (tid < 40) slinb[tid] = linB[tid];
    }
    __syncthreads();

    // softmax(lam1), softmax(lam2) — tiny, recompute per thread
    float e0 = __expf(lam1[0]), e1 = __expf(lam1[1]);
    float lamxl = e0 / (e0 + e1), laml = e1 / (e0 + e1);
    float f0 = __expf(lam2[0]), f1 = __expf(lam2[1]);
    float lamxh = f0 / (f0 + f1), lamh = f1 / (f0 + f1);

    int warp = tid >> 5, l = tid & 31;
    int node = blockIdx.x * 8 + warp;
    if (node >= n) return;

    int base = node * 64;
    float xl0 = g_xl[base + l], xl1 = g_xl[base + l + 32];
    float xh0 = g_xh[base + l], xh1 = g_xh[base + l + 32];
    float xv0 = x[base + l],    xv1 = x[base + l + 32];
    float2 d = g_D2[node];
    float dll2 = d.x * d.x, dhh2 = d.y * d.y;
    float a20 = g_y2[base + l] + dll2 * xl0, a21 = g_y2[base + l + 32] + dll2 * xl1;
    float a40 = g_y4[base + l] + dhh2 * xh0, a41 = g_y4[base + l + 32] + dhh2 * xh1;

    float z20 = 0.f, z21 = 0.f, z40 = 0.f, z41 = 0.f, m0 = 0.f, m1 = 0.f;
    const unsigned msk = 0xffffffffu;
#pragma unroll
    for (int k = 0; k < 32; k++) {
        float b2  = __shfl_sync(msk, a20, k);
        float b4  = __shfl_sync(msk, a40, k);
        float bxl = __shfl_sync(msk, xl0, k);
        float bxh = __shfl_sync(msk, xh0, k);
        float bx  = __shfl_sync(msk, xv0, k);
        int o = k * 64;
        z20 += b2 * s2l[o + l]      + bxl * s2r[o + l];
        z21 += b2 * s2l[o + l + 32] + bxl * s2r[o + l + 32];
        z40 += b4 * s4l[o + l]      + bxh * s4r[o + l];
        z41 += b4 * s4l[o + l + 32] + bxh * s4r[o + l + 32];
        m0  += bx * sx[o + l];
        m1  += bx * sx[o + l + 32];
    }
#pragma unroll
    for (int k = 0; k < 32; k++) {
        float b2  = __shfl_sync(msk, a21, k);
        float b4  = __shfl_sync(msk, a41, k);
        float bxl = __shfl_sync(msk, xl1, k);
        float bxh = __shfl_sync(msk, xh1, k);
        float bx  = __shfl_sync(msk, xv1, k);
        int o = (k + 32) * 64;
        z20 += b2 * s2l[o + l]      + bxl * s2r[o + l];
        z21 += b2 * s2l[o + l + 32] + bxl * s2r[o + l + 32];
        z40 += b4 * s4l[o + l]      + bxh * s4r[o + l];
        z41 += b4 * s4l[o + l + 32] + bxh * s4r[o + l + 32];
        m0  += bx * sx[o + l];
        m1  += bx * sx[o + l + 32];
    }

    int cci = __ldg(cc + node);
    float lamx = cci ? lamxl : lamxh;
    float xf0 = fmaxf(lamx * m0 + laml * z20 + lamh * z40, 0.f);
    float xf1 = fmaxf(lamx * m1 + laml * z21 + lamh * z41, 0.f);

    float* st = sstg + warp * 64;
    st[l] = xf0;
    st[l + 32] = xf1;
    __syncwarp();

    float acc0 = slinb[l];                       // out[l], l in [0,32)
    float acc1 = (l < 8) ? slinb[32 + l] : 0.f;  // out[32+l], l in [0,8)
#pragma unroll
    for (int k = 0; k < 64; k++) {
        float b = st[k];
        acc0 += b * slin[k * 40 + l];
        if (l < 8) acc1 += b * slin[k * 40 + 32 + l];
    }
    out[node * 40 + l] = acc0;
    if (l < 8) out[node * 40 + 32 + l] = acc1;
}

// ---------------- host launcher --------------------------------------------
extern "C" void kernel_launch(void* const* d_in, const int* in_sizes, int n_in,
                              void* d_out, int out_size) {
    const float* x    = (const float*)d_in[0];
    const int*   ei   = (const int*)d_in[1];
    const int*   cc   = (const int*)d_in[2];
    const float* W1l  = (const float*)d_in[3];
    const float* W1r  = (const float*)d_in[4];
    const float* W2l  = (const float*)d_in[5];
    const float* W2r  = (const float*)d_in[6];
    const float* W3l  = (const float*)d_in[7];
    const float* W3r  = (const float*)d_in[8];
    const float* W4l  = (const float*)d_in[9];
    const float* W4r  = (const float*)d_in[10];
    const float* WX   = (const float*)d_in[11];
    const float* lam1 = (const float*)d_in[12];
    const float* lam2 = (const float*)d_in[13];
    const float* linW = (const float*)d_in[14];
    const float* linB = (const float*)d_in[15];
    float* out = (float*)d_out;

    int n = in_sizes[0] / 64;
    int E = in_sizes[1] / 2;
    const int* col = ei;       // SparseTensor(row=ei[1], col=ei[0])
    const int* row = ei + E;

    cudaFuncSetAttribute(k_dense1, cudaFuncAttributeMaxDynamicSharedMemorySize, 65536);
    cudaFuncSetAttribute(k_dense2, cudaFuncAttributeMaxDynamicSharedMemorySize, 94368);

    k_zero<<<2048, 256>>>(n);
    k_deg<<<(E + 255) / 256, 256>>>(col, row, cc, E);
    k_coef<<<(n + 255) / 256, 256>>>(cc, n);
    int spmm_blocks = (E * 16 + 255) / 256;
    k_spmm<0><<<spmm_blocks, 256>>>(col, row, cc, x, E);
    k_dense1<<<(n + 7) / 8, 256, 65536>>>(x, W1l, W1r, W3l, W3r, n);
    k_spmm<1><<<spmm_blocks, 256>>>(col, row, cc, x, E);
    k_dense2<<<(n + 7) / 8, 256, 94368>>>(x, cc, W2l, W2r, W4l, W4r, WX,
                                          lam1, lam2, linW, linB, out, n);
}

// round 2
// speedup vs baseline: 1.8018x; 1.8018x over previous
#include <cuda_runtime.h>

#define NMAX 100000
#define EMAX 1600000

// ---------------- scratch (device globals; no allocation allowed) ----------
__device__ float g_y1[NMAX * 64];
__device__ float g_y2[NMAX * 64];
__device__ float g_y3[NMAX * 64];
__device__ float g_y4[NMAX * 64];
__device__ float g_xl[NMAX * 64];   // dense1 output xl; later overwritten with xf
__device__ float g_xh[NMAX * 64];
__device__ float2 g_D1[NMAX];
__device__ float2 g_D2[NMAX];
__device__ int    g_cnt[NMAX];
__device__ int    g_s[NMAX];

// ---------------- zero scratch each replay ---------------------------------
__global__ void k_zero(int n) {
    int stride = gridDim.x * blockDim.x;
    int i0 = blockIdx.x * blockDim.x + threadIdx.x;
    int nv = n * 16;
    float4 z = make_float4(0.f, 0.f, 0.f, 0.f);
    float4* y1 = (float4*)g_y1;
    float4* y2 = (float4*)g_y2;
    float4* y3 = (float4*)g_y3;
    float4* y4 = (float4*)g_y4;
    for (int i = i0; i < nv; i += stride) {
        y1[i] = z; y2[i] = z; y3[i] = z; y4[i] = z;
    }
    for (int i = i0; i < n; i += stride) { g_cnt[i] = 0; g_s[i] = 0; }
}

// ---------------- degree pass ----------------------------------------------
__global__ void k_deg(const int* __restrict__ col, const int* __restrict__ row,
                      const int* __restrict__ cc, int E) {
    int e = blockIdx.x * blockDim.x + threadIdx.x;
    if (e >= E) return;
    int r = __ldg(row + e);
    int c = __ldg(col + e);
    if (r == c) return;
    atomicAdd(&g_cnt[r], 1);
    atomicAdd(&g_s[r], __ldg(cc + c));
}

// ---------------- normalization coefficients -------------------------------
__global__ void k_coef(const int* __restrict__ cc, int n) {
    int i = blockIdx.x * blockDim.x + threadIdx.x;
    if (i >= n) return;
    float cnt = (float)g_cnt[i];
    float sv  = (float)g_s[i];
    int cci = __ldg(cc + i);
    float dl  = rsqrtf((cci ? cnt : 0.f) + 1.f);
    float dh  = rsqrtf((cci ? 0.f : cnt) + 1.f);
    float dll = rsqrtf(sv + 1.f);
    float dhh = rsqrtf(cnt - sv + 1.f);
    g_D1[i] = make_float2(dl, dh);
    g_D2[i] = make_float2(dll, dhh);
}

// ---------------- fused dual-channel SpMM (16 lanes per edge) --------------
template <int PASS>
__global__ void __launch_bounds__(256) k_spmm(const int* __restrict__ col,
                                              const int* __restrict__ row,
                                              const int* __restrict__ cc,
                                              const float* __restrict__ x,
                                              int E) {
    int t = blockIdx.x * blockDim.x + threadIdx.x;
    int e = t >> 4;
    if (e >= E) return;
    int p = t & 15;
    int r = __ldg(row + e);
    int c = __ldg(col + e);
    if (r == c) return;

    const float2* D = (PASS == 0) ? g_D1 : g_D2;
    int sel = __ldg(cc + ((PASS == 0) ? r : c));
    float2 dr = __ldg(D + r);
    float2 dc = __ldg(D + c);

    float w;
    const float* src;
    float* dst;
    if (sel) {
        w = dr.x * dc.x;
        src = (PASS == 0) ? x : g_xl;
        dst = (PASS == 0) ? g_y1 : g_y2;
    } else {
        w = dr.y * dc.y;
        src = (PASS == 0) ? x : g_xh;
        dst = (PASS == 0) ? g_y3 : g_y4;
    }

    float4 v = __ldg((const float4*)(src + c * 64) + p);
    v.x *= w; v.y *= w; v.z *= w; v.w *= w;
    atomicAdd((float4*)(dst + r * 64) + p, v);
}

// ---------------- dense layer 1 (register-tiled GEMM) ----------------------
// Block: 256 threads, 128 nodes. Thread: 4 nodes x 8 outputs x 2 channels.
// smem: W1l,W1r,W3l,W3r (4*4096 floats) + 2 activation buffers [128][33].
#define D1_SMEM_FLOATS (4 * 4096 + 2 * 128 * 33)
__global__ void __launch_bounds__(256, 2) k_dense1(const float* __restrict__ x,
                                                   const float* __restrict__ W1l,
                                                   const float* __restrict__ W1r,
                                                   const float* __restrict__ W3l,
                                                   const float* __restrict__ W3r,
                                                   int n) {
    extern __shared__ float s[];
    float* sw1l = s;
    float* sw1r = s + 4096;
    float* sw3l = s + 8192;
    float* sw3r = s + 12288;
    float* bufA = s + 16384;            // 128*33
    float* bufB = s + 16384 + 128 * 33; // 128*33

    int tid = threadIdx.x;
    {
        float4* d4 = (float4*)s;
        for (int i = tid; i < 4096; i += 256) {
            const float* srcm = (i < 1024) ? W1l : (i < 2048) ? W1r : (i < 3072) ? W3l : W3r;
            d4[i] = ((const float4*)srcm)[i & 1023];
        }
    }

    int tn = tid & 7;      // output group: outs tn*8 .. tn*8+7
    int tm = tid >> 3;     // node group:   nodes tm*4 .. tm*4+3 (local)
    int nbase = blockIdx.x * 128;

    float accL[4][8], accH[4][8];
#pragma unroll
    for (int i = 0; i < 4; i++)
#pragma unroll
        for (int j = 0; j < 8; j++) { accL[i][j] = 0.f; accH[i][j] = 0.f; }

    // ---- phase 1: agg1 @ W1l, agg3 @ W3l (k = 0..63 in 2 chunks of 32) ----
    for (int c = 0; c < 2; c++) {
        __syncthreads();
        for (int it = tid; it < 1024; it += 256) {
            int nl = it >> 3, f4 = it & 7;
            int node = nbase + nl;
            int kg = c * 32 + f4 * 4;
            float4 xv = make_float4(0.f, 0.f, 0.f, 0.f), y1v = xv, y3v = xv;
            float dl2 = 0.f, dh2 = 0.f;
            if (node < n) {
                xv  = __ldg((const float4*)(x + node * 64 + kg));
                y1v = *((const float4*)(g_y1 + node * 64 + kg));
                y3v = *((const float4*)(g_y3 + node * 64 + kg));
                float2 d = g_D1[node];
                dl2 = d.x * d.x; dh2 = d.y * d.y;
            }
            int sb = nl * 33 + f4 * 4;
            bufA[sb + 0] = y1v.x + dl2 * xv.x;
            bufA[sb + 1] = y1v.y + dl2 * xv.y;
            bufA[sb + 2] = y1v.z + dl2 * xv.z;
            bufA[sb + 3] = y1v.w + dl2 * xv.w;
            bufB[sb + 0] = y3v.x + dh2 * xv.x;
            bufB[sb + 1] = y3v.y + dh2 * xv.y;
            bufB[sb + 2] = y3v.z + dh2 * xv.z;
            bufB[sb + 3] = y3v.w + dh2 * xv.w;
        }
        __syncthreads();
        const float* wl = sw1l + c * 32 * 64;
        const float* wh = sw3l + c * 32 * 64;
#pragma unroll 8
        for (int k = 0; k < 32; k++) {
            float a1[4], a3[4];
#pragma unroll
            for (int i = 0; i < 4; i++) {
                a1[i] = bufA[(tm * 4 + i) * 33 + k];
                a3[i] = bufB[(tm * 4 + i) * 33 + k];
            }
            float4 l0 = *(const float4*)(wl + k * 64 + tn * 8);
            float4 l1 = *(const float4*)(wl + k * 64 + tn * 8 + 4);
            float4 h0 = *(const float4*)(wh + k * 64 + tn * 8);
            float4 h1 = *(const float4*)(wh + k * 64 + tn * 8 + 4);
#pragma unroll
            for (int i = 0; i < 4; i++) {
                accL[i][0] += a1[i] * l0.x; accL[i][1] += a1[i] * l0.y;
                accL[i][2] += a1[i] * l0.z; accL[i][3] += a1[i] * l0.w;
                accL[i][4] += a1[i] * l1.x; accL[i][5] += a1[i] * l1.y;
                accL[i][6] += a1[i] * l1.z; accL[i][7] += a1[i] * l1.w;
                accH[i][0] += a3[i] * h0.x; accH[i][1] += a3[i] * h0.y;
                accH[i][2] += a3[i] * h0.z; accH[i][3] += a3[i] * h0.w;
                accH[i][4] += a3[i] * h1.x; accH[i][5] += a3[i] * h1.y;
                accH[i][6] += a3[i] * h1.z; accH[i][7] += a3[i] * h1.w;
            }
        }
    }

    // ---- phase 2: x @ W1r, x @ W3r ----
    for (int c = 0; c < 2; c++) {
        __syncthreads();
        for (int it = tid; it < 1024; it += 256) {
            int nl = it >> 3, f4 = it & 7;
            int node = nbase + nl;
            int kg = c * 32 + f4 * 4;
            float4 xv = make_float4(0.f, 0.f, 0.f, 0.f);
            if (node < n) xv = __ldg((const float4*)(x + node * 64 + kg));
            int sb = nl * 33 + f4 * 4;
            bufA[sb + 0] = xv.x; bufA[sb + 1] = xv.y;
            bufA[sb + 2] = xv.z; bufA[sb + 3] = xv.w;
        }
        __syncthreads();
        const float* wl = sw1r + c * 32 * 64;
        const float* wh = sw3r + c * 32 * 64;
#pragma unroll 8
        for (int k = 0; k < 32; k++) {
            float a[4];
#pragma unroll
            for (int i = 0; i < 4; i++) a[i] = bufA[(tm * 4 + i) * 33 + k];
            float4 l0 = *(const float4*)(wl + k * 64 + tn * 8);
            float4 l1 = *(const float4*)(wl + k * 64 + tn * 8 + 4);
            float4 h0 = *(const float4*)(wh + k * 64 + tn * 8);
            float4 h1 = *(const float4*)(wh + k * 64 + tn * 8 + 4);
#pragma unroll
            for (int i = 0; i < 4; i++) {
                accL[i][0] += a[i] * l0.x; accL[i][1] += a[i] * l0.y;
                accL[i][2] += a[i] * l0.z; accL[i][3] += a[i] * l0.w;
                accL[i][4] += a[i] * l1.x; accL[i][5] += a[i] * l1.y;
                accL[i][6] += a[i] * l1.z; accL[i][7] += a[i] * l1.w;
                accH[i][0] += a[i] * h0.x; accH[i][1] += a[i] * h0.y;
                accH[i][2] += a[i] * h0.z; accH[i][3] += a[i] * h0.w;
                accH[i][4] += a[i] * h1.x; accH[i][5] += a[i] * h1.y;
                accH[i][6] += a[i] * h1.z; accH[i][7] += a[i] * h1.w;
            }
        }
    }

    // ---- epilogue: relu, store xl/xh ----
#pragma unroll
    for (int i = 0; i < 4; i++) {
        int node = nbase + tm * 4 + i;
        if (node >= n) continue;
        float4 v0, v1;
        v0.x = fmaxf(accL[i][0], 0.f); v0.y = fmaxf(accL[i][1], 0.f);
        v0.z = fmaxf(accL[i][2], 0.f); v0.w = fmaxf(accL[i][3], 0.f);
        v1.x = fmaxf(accL[i][4], 0.f); v1.y = fmaxf(accL[i][5], 0.f);
        v1.z = fmaxf(accL[i][6], 0.f); v1.w = fmaxf(accL[i][7], 0.f);
        *((float4*)(g_xl + node * 64 + tn * 8))     = v0;
        *((float4*)(g_xl + node * 64 + tn * 8 + 4)) = v1;
        v0.x = fmaxf(accH[i][0], 0.f); v0.y = fmaxf(accH[i][1], 0.f);
        v0.z = fmaxf(accH[i][2], 0.f); v0.w = fmaxf(accH[i][3], 0.f);
        v1.x = fmaxf(accH[i][4], 0.f); v1.y = fmaxf(accH[i][5], 0.f);
        v1.z = fmaxf(accH[i][6], 0.f); v1.w = fmaxf(accH[i][7], 0.f);
        *((float4*)(g_xh + node * 64 + tn * 8))     = v0;
        *((float4*)(g_xh + node * 64 + tn * 8 + 4)) = v1;
    }
}

// ---------------- dense layer 2 GEMM + mix (register-tiled) ----------------
// Block: 256 threads, 64 nodes. Thread: 4 nodes x 4 outputs x 3 accumulators.
// Writes xf (post-relu mix) into g_xl in place.
#define D2_SMEM_FLOATS (5 * 4096 + 2 * 64 * 33)
__global__ void __launch_bounds__(256, 2) k_dense2(const float* __restrict__ x,
                                                   const int* __restrict__ cc,
                                                   const float* __restrict__ W2l,
                                                   const float* __restrict__ W2r,
                                                   const float* __restrict__ W4l,
                                                   const float* __restrict__ W4r,
                                                   const float* __restrict__ WX,
                                                   const float* __restrict__ lam1,
                                                   const float* __restrict__ lam2,
                                                   int n) {
    extern __shared__ float s[];
    float* sw2l = s;
    float* sw2r = s + 4096;
    float* sw4l = s + 8192;
    float* sw4r = s + 12288;
    float* swx  = s + 16384;
    float* bufA = s + 20480;           // 64*33
    float* bufB = s + 20480 + 64 * 33; // 64*33

    int tid = threadIdx.x;
    {
        float4* d4 = (float4*)s;
        for (int i = tid; i < 5120; i += 256) {
            const float* srcm = (i < 1024) ? W2l : (i < 2048) ? W2r :
                                (i < 3072) ? W4l : (i < 4096) ? W4r : WX;
            d4[i] = ((const float4*)srcm)[i & 1023];
        }
    }

    int tn = tid & 15;    // outs tn*4 .. tn*4+3
    int tm = tid >> 4;    // nodes tm*4 .. tm*4+3 (local, 16 groups * 4 = 64)
    int nbase = blockIdx.x * 64;

    float accZ2[4][4], accZ4[4][4], accM[4][4];
#pragma unroll
    for (int i = 0; i < 4; i++)
#pragma unroll
        for (int j = 0; j < 4; j++) { accZ2[i][j] = 0.f; accZ4[i][j] = 0.f; accM[i][j] = 0.f; }

    // ---- phase 1: agg2 @ W2l, agg4 @ W4l ----
    for (int c = 0; c < 2; c++) {
        __syncthreads();
        for (int it = tid; it < 512; it += 256) {
            int nl = it >> 3, f4 = it & 7;
            int node = nbase + nl;
            int kg = c * 32 + f4 * 4;
            float4 xlv = make_float4(0.f, 0.f, 0.f, 0.f), xhv = xlv, y2v = xlv, y4v = xlv;
            float dll2 = 0.f, dhh2 = 0.f;
            if (node < n) {
                xlv = *((const float4*)(g_xl + node * 64 + kg));
                xhv = *((const float4*)(g_xh + node * 64 + kg));
                y2v = *((const float4*)(g_y2 + node * 64 + kg));
                y4v = *((const float4*)(g_y4 + node * 64 + kg));
                float2 d = g_D2[node];
                dll2 = d.x * d.x; dhh2 = d.y * d.y;
            }
            int sb = nl * 33 + f4 * 4;
            bufA[sb + 0] = y2v.x + dll2 * xlv.x;
            bufA[sb + 1] = y2v.y + dll2 * xlv.y;
            bufA[sb + 2] = y2v.z + dll2 * xlv.z;
            bufA[sb + 3] = y2v.w + dll2 * xlv.w;
            bufB[sb + 0] = y4v.x + dhh2 * xhv.x;
            bufB[sb + 1] = y4v.y + dhh2 * xhv.y;
            bufB[sb + 2] = y4v.z + dhh2 * xhv.z;
            bufB[sb + 3] = y4v.w + dhh2 * xhv.w;
        }
        __syncthreads();
        const float* w2 = sw2l + c * 32 * 64;
        const float* w4 = sw4l + c * 32 * 64;
#pragma unroll 8
        for (int k = 0; k < 32; k++) {
            float a2[4], a4[4];
#pragma unroll
            for (int i = 0; i < 4; i++) {
                a2[i] = bufA[(tm * 4 + i) * 33 + k];
                a4[i] = bufB[(tm * 4 + i) * 33 + k];
            }
            float4 wz2 = *(const float4*)(w2 + k * 64 + tn * 4);
            float4 wz4 = *(const float4*)(w4 + k * 64 + tn * 4);
#pragma unroll
            for (int i = 0; i < 4; i++) {
                accZ2[i][0] += a2[i] * wz2.x; accZ2[i][1] += a2[i] * wz2.y;
                accZ2[i][2] += a2[i] * wz2.z; accZ2[i][3] += a2[i] * wz2.w;
                accZ4[i][0] += a4[i] * wz4.x; accZ4[i][1] += a4[i] * wz4.y;
                accZ4[i][2] += a4[i] * wz4.z; accZ4[i][3] += a4[i] * wz4.w;
            }
        }
    }

    // ---- phase 2: xl @ W2r, xh @ W4r ----
    for (int c = 0; c < 2; c++) {
        __syncthreads();
        for (int it = tid; it < 512; it += 256) {
            int nl = it >> 3, f4 = it & 7;
            int node = nbase + nl;
            int kg = c * 32 + f4 * 4;
            float4 xlv = make_float4(0.f, 0.f, 0.f, 0.f), xhv = xlv;
            if (node < n) {
                xlv = *((const float4*)(g_xl + node * 64 + kg));
                xhv = *((const float4*)(g_xh + node * 64 + kg));
            }
            int sb = nl * 33 + f4 * 4;
            bufA[sb + 0] = xlv.x; bufA[sb + 1] = xlv.y;
            bufA[sb + 2] = xlv.z; bufA[sb + 3] = xlv.w;
            bufB[sb + 0] = xhv.x; bufB[sb + 1] = xhv.y;
            bufB[sb + 2] = xhv.z; bufB[sb + 3] = xhv.w;
        }
        __syncthreads();
        const float* w2 = sw2r + c * 32 * 64;
        const float* w4 = sw4r + c * 32 * 64;
#pragma unroll 8
        for (int k = 0; k < 32; k++) {
            float a2[4], a4[4];
#pragma unroll
            for (int i = 0; i < 4; i++) {
                a2[i] = bufA[(tm * 4 + i) * 33 + k];
                a4[i] = bufB[(tm * 4 + i) * 33 + k];
            }
            float4 wz2 = *(const float4*)(w2 + k * 64 + tn * 4);
            float4 wz4 = *(const float4*)(w4 + k * 64 + tn * 4);
#pragma unroll
            for (int i = 0; i < 4; i++) {
                accZ2[i][0] += a2[i] * wz2.x; accZ2[i][1] += a2[i] * wz2.y;
                accZ2[i][2] += a2[i] * wz2.z; accZ2[i][3] += a2[i] * wz2.w;
                accZ4[i][0] += a4[i] * wz4.x; accZ4[i][1] += a4[i] * wz4.y;
                accZ4[i][2] += a4[i] * wz4.z; accZ4[i][3] += a4[i] * wz4.w;
            }
        }
    }

    // ---- phase 3: x @ WX ----
    for (int c = 0; c < 2; c++) {
        __syncthreads();
        for (int it = tid; it < 512; it += 256) {
            int nl = it >> 3, f4 = it & 7;
            int node = nbase + nl;
            int kg = c * 32 + f4 * 4;
            float4 xv = make_float4(0.f, 0.f, 0.f, 0.f);
            if (node < n) xv = __ldg((const float4*)(x + node * 64 + kg));
            int sb = nl * 33 + f4 * 4;
            bufA[sb + 0] = xv.x; bufA[sb + 1] = xv.y;
            bufA[sb + 2] = xv.z; bufA[sb + 3] = xv.w;
        }
        __syncthreads();
        const float* wm = swx + c * 32 * 64;
#pragma unroll 8
        for (int k = 0; k < 32; k++) {
            float a[4];
#pragma unroll
            for (int i = 0; i < 4; i++) a[i] = bufA[(tm * 4 + i) * 33 + k];
            float4 wv = *(const float4*)(wm + k * 64 + tn * 4);
#pragma unroll
            for (int i = 0; i < 4; i++) {
                accM[i][0] += a[i] * wv.x; accM[i][1] += a[i] * wv.y;
                accM[i][2] += a[i] * wv.z; accM[i][3] += a[i] * wv.w;
            }
        }
    }

    // ---- epilogue: mix + relu -> xf stored into g_xl ----
    float e0 = __expf(lam1[0]), e1 = __expf(lam1[1]);
    float lamxl = e0 / (e0 + e1), laml = e1 / (e0 + e1);
    float f0 = __expf(lam2[0]), f1 = __expf(lam2[1]);
    float lamxh = f0 / (f0 + f1), lamh = f1 / (f0 + f1);

#pragma unroll
    for (int i = 0; i < 4; i++) {
        int node = nbase + tm * 4 + i;
        if (node >= n) continue;
        float lamx = __ldg(cc + node) ? lamxl : lamxh;
        float4 v;
        v.x = fmaxf(lamx * accM[i][0] + laml * accZ2[i][0] + lamh * accZ4[i][0], 0.f);
        v.y = fmaxf(lamx * accM[i][1] + laml * accZ2[i][1] + lamh * accZ4[i][1], 0.f);
        v.z = fmaxf(lamx * accM[i][2] + laml * accZ2[i][2] + lamh * accZ4[i][2], 0.f);
        v.w = fmaxf(lamx * accM[i][3] + laml * accZ2[i][3] + lamh * accZ4[i][3], 0.f);
        *((float4*)(g_xl + node * 64 + tn * 4)) = v;
    }
}

// ---------------- classifier: out = xf @ linW + linB -----------------------
__global__ void __launch_bounds__(256) k_cls(const float* __restrict__ linW,
                                             const float* __restrict__ linB,
                                             float* __restrict__ out, int n) {
    __shared__ float slin[2560];
    __shared__ float slinb[40];
    int tid = threadIdx.x;
    for (int i = tid; i < 2560; i += 256) slin[i] = linW[i];
    if (tid < 40) slinb[tid] = linB[tid];
    __syncthreads();

    int warp = tid >> 5, l = tid & 31;
    int node = blockIdx.x * 8 + warp;
    if (node >= n) return;
    int base = node * 64;
    float xf0 = g_xl[base + l], xf1 = g_xl[base + l + 32];

    float acc0 = slinb[l];
    float acc1 = (l < 8) ? slinb[32 + l] : 0.f;
    const unsigned m = 0xffffffffu;
#pragma unroll
    for (int k = 0; k < 32; k++) {
        float b = __shfl_sync(m, xf0, k);
        acc0 += b * slin[k * 40 + l];
        if (l < 8) acc1 += b * slin[k * 40 + 32 + l];
    }
#pragma unroll
    for (int k = 0; k < 32; k++) {
        float b = __shfl_sync(m, xf1, k);
        int o = (k + 32) * 40;
        acc0 += b * slin[o + l];
        if (l < 8) acc1 += b * slin[o + 32 + l];
    }
    out[node * 40 + l] = acc0;
    if (l < 8) out[node * 40 + 32 + l] = acc1;
}

// ---------------- host launcher --------------------------------------------
extern "C" void kernel_launch(void* const* d_in, const int* in_sizes, int n_in,
                              void* d_out, int out_size) {
    const float* x    = (const float*)d_in[0];
    const int*   ei   = (const int*)d_in[1];
    const int*   cc   = (const int*)d_in[2];
    const float* W1l  = (const float*)d_in[3];
    const float* W1r  = (const float*)d_in[4];
    const float* W2l  = (const float*)d_in[5];
    const float* W2r  = (const float*)d_in[6];
    const float* W3l  = (const float*)d_in[7];
    const float* W3r  = (const float*)d_in[8];
    const float* W4l  = (const float*)d_in[9];
    const float* W4r  = (const float*)d_in[10];
    const float* WX   = (const float*)d_in[11];
    const float* lam1 = (const float*)d_in[12];
    const float* lam2 = (const float*)d_in[13];
    const float* linW = (const float*)d_in[14];
    const float* linB = (const float*)d_in[15];
    float* out = (float*)d_out;

    int n = in_sizes[0] / 64;
    int E = in_sizes[1] / 2;
    const int* col = ei;
    const int* row = ei + E;

    cudaFuncSetAttribute(k_dense1, cudaFuncAttributeMaxDynamicSharedMemorySize,
                         D1_SMEM_FLOATS * 4);
    cudaFuncSetAttribute(k_dense2, cudaFuncAttributeMaxDynamicSharedMemorySize,
                         D2_SMEM_FLOATS * 4);

    k_zero<<<2048, 256>>>(n);
    k_deg<<<(E + 255) / 256, 256>>>(col, row, cc, E);
    k_coef<<<(n + 255) / 256, 256>>>(cc, n);
    int spmm_blocks = (E * 16 + 255) / 256;
    k_spmm<0><<<spmm_blocks, 256>>>(col, row, cc, x, E);
    k_dense1<<<(n + 127) / 128, 256, D1_SMEM_FLOATS * 4>>>(x, W1l, W1r, W3l, W3r, n);
    k_spmm<1><<<spmm_blocks, 256>>>(col, row, cc, x, E);
    k_dense2<<<(n + 63) / 64, 256, D2_SMEM_FLOATS * 4>>>(x, cc, W2l, W2r, W4l, W4r,
                                                         WX, lam1, lam2, n);
    k_cls<<<(n + 7) / 8, 256>>>(linW, linB, out, n);
}

// round 3
// speedup vs baseline: 2.0411x; 1.1328x over previous
#include <cuda_runtime.h>

#define NMAX 100000
#define EMAX 1600000

// ---------------- scratch (device globals; no allocation allowed) ----------
__device__ float g_y1[NMAX * 64];
__device__ float g_y2[NMAX * 64];
__device__ float g_y3[NMAX * 64];
__device__ float g_y4[NMAX * 64];
__device__ float g_xl[NMAX * 64];   // dense1 output xl; later overwritten with xf
__device__ float g_xh[NMAX * 64];
__device__ float2 g_D1[NMAX];
__device__ float2 g_D2[NMAX];
__device__ int    g_cnt[NMAX];
__device__ int    g_s[NMAX];
__device__ int    g_ptr[NMAX];
__device__ int    g_pos[NMAX];
__device__ int    g_adj[EMAX];
__device__ int    g_bsum[128];
__device__ int    g_boff[128];

// ---------------- tiny zero (cnt/s only; feature buffers no longer zeroed) -
__global__ void k_zero_small(int n) {
    int i = blockIdx.x * blockDim.x + threadIdx.x;
    if (i < n) { g_cnt[i] = 0; g_s[i] = 0; }
}

// ---------------- degree pass ----------------------------------------------
__global__ void k_deg(const int* __restrict__ col, const int* __restrict__ row,
                      const int* __restrict__ cc, int E) {
    int e = blockIdx.x * blockDim.x + threadIdx.x;
    if (e >= E) return;
    int r = __ldg(row + e);
    int c = __ldg(col + e);
    if (r == c) return;
    atomicAdd(&g_cnt[r], 1);
    atomicAdd(&g_s[r], __ldg(cc + c));
}

// ---------------- scan kernel A: per-1024-chunk sums ------------------------
__global__ void k_scanA(int n) {
    __shared__ int sm[1024];
    int tid = threadIdx.x;
    int i = blockIdx.x * 1024 + tid;
    int v = (i < n) ? g_cnt[i] : 0;
    sm[tid] = v;
    __syncthreads();
    for (int off = 512; off; off >>= 1) {
        if (tid < off) sm[tid] += sm[tid + off];
        __syncthreads();
    }
    if (tid == 0) g_bsum[blockIdx.x] = sm[0];
}

// ---------------- scan kernel B: exclusive scan of block sums (1 block) ----
__global__ void k_scanB(int nb) {
    int t = threadIdx.x;                 // 128 threads
    int lane = t & 31, w = t >> 5;
    int v = (t < nb) ? g_bsum[t] : 0;
    int xv = v;
    const unsigned F = 0xffffffffu;
#pragma unroll
    for (int o = 1; o < 32; o <<= 1) {
        int y = __shfl_up_sync(F, xv, o);
        if (lane >= o) xv += y;
    }
    __shared__ int ws[4];
    if (lane == 31) ws[w] = xv;
    __syncthreads();
    __shared__ int wo[4];
    if (t == 0) {
        int a = 0;
        for (int i = 0; i < 4; i++) { wo[i] = a; a += ws[i]; }
    }
    __syncthreads();
    if (t < 128) g_boff[t] = xv + wo[w] - v;   // exclusive
}

// ---------------- scan kernel C: final ptr/pos + coefficients ---------------
__global__ void k_scanC(const int* __restrict__ cc, int n) {
    __shared__ int ws[32];
    int tid = threadIdx.x;
    int lane = tid & 31, w = tid >> 5;
    int i = blockIdx.x * 1024 + tid;
    int v = (i < n) ? g_cnt[i] : 0;
    int xv = v;
    const unsigned F = 0xffffffffu;
#pragma unroll
    for (int o = 1; o < 32; o <<= 1) {
        int y = __shfl_up_sync(F, xv, o);
        if (lane >= o) xv += y;
    }
    if (lane == 31) ws[w] = xv;
    __syncthreads();
    if (w == 0) {
        int t2 = ws[lane];
        int sv = t2;
#pragma unroll
        for (int o = 1; o < 32; o <<= 1) {
            int y = __shfl_up_sync(F, sv, o);
            if (lane >= o) sv += y;
        }
        ws[lane] = sv - t2;   // exclusive warp offsets
    }
    __syncthreads();
    if (i < n) {
        int ptr = g_boff[blockIdx.x] + ws[w] + xv - v;
        g_ptr[i] = ptr;
        g_pos[i] = ptr;
        // fused coefficient computation
        float cnt = (float)v;
        float sv2 = (float)g_s[i];
        int cci = __ldg(cc + i);
        float dl  = rsqrtf((cci ? cnt : 0.f) + 1.f);
        float dh  = rsqrtf((cci ? 0.f : cnt) + 1.f);
        float dll = rsqrtf(sv2 + 1.f);
        float dhh = rsqrtf(cnt - sv2 + 1.f);
        g_D1[i] = make_float2(dl, dh);
        g_D2[i] = make_float2(dll, dhh);
    }
}

// ---------------- scatter: build adjacency ----------------------------------
__global__ void k_scatter(const int* __restrict__ col, const int* __restrict__ row,
                          const int* __restrict__ cc, int E) {
    int e = blockIdx.x * blockDim.x + threadIdx.x;
    if (e >= E) return;
    int r = __ldg(row + e);
    int c = __ldg(col + e);
    if (r == c) return;
    int p = atomicAdd(&g_pos[r], 1);
    g_adj[p] = (c << 1) | __ldg(cc + c);
}

// ---------------- gather pass 0: y1/y3 = off-diag agg (channel by cc[row]) -
__global__ void __launch_bounds__(256) k_gather0(const int* __restrict__ cc,
                                                 const float* __restrict__ x,
                                                 int n) {
    int tid = threadIdx.x;
    int warp = tid >> 5, l = tid & 31;
    int r = blockIdx.x * 8 + warp;
    if (r >= n) return;

    int ccr = __ldg(cc + r);
    float2 d1r = g_D1[r];
    float drv = ccr ? d1r.x : d1r.y;
    int start = g_ptr[r];
    int deg = g_cnt[r];

    float a0 = 0.f, a1 = 0.f;
    const unsigned F = 0xffffffffu;
    for (int j0 = 0; j0 < deg; j0 += 32) {
        int myp = 0;
        if (j0 + l < deg) myp = __ldg(g_adj + start + j0 + l);
        int kmax = min(32, deg - j0);
        for (int k = 0; k < kmax; k++) {
            int packed = __shfl_sync(F, myp, k);
            int c = packed >> 1;
            float2 d1c = g_D1[c];
            float w = drv * (ccr ? d1c.x : d1c.y);
            a0 += w * __ldg(x + c * 64 + l);
            a1 += w * __ldg(x + c * 64 + l + 32);
        }
    }
    int base = r * 64;
    if (ccr) {
        g_y1[base + l] = a0;  g_y1[base + l + 32] = a1;
        g_y3[base + l] = 0.f; g_y3[base + l + 32] = 0.f;
    } else {
        g_y3[base + l] = a0;  g_y3[base + l + 32] = a1;
        g_y1[base + l] = 0.f; g_y1[base + l + 32] = 0.f;
    }
}

// ---------------- gather pass 1: y2/y4 (channel by cc[col]) ----------------
__global__ void __launch_bounds__(256) k_gather1(int n) {
    int tid = threadIdx.x;
    int warp = tid >> 5, l = tid & 31;
    int r = blockIdx.x * 8 + warp;
    if (r >= n) return;

    float2 d2r = g_D2[r];
    float dllr = d2r.x, dhhr = d2r.y;
    int start = g_ptr[r];
    int deg = g_cnt[r];

    float a20 = 0.f, a21 = 0.f, a40 = 0.f, a41 = 0.f;
    const unsigned F = 0xffffffffu;
    for (int j0 = 0; j0 < deg; j0 += 32) {
        int myp = 0;
        if (j0 + l < deg) myp = __ldg(g_adj + start + j0 + l);
        int kmax = min(32, deg - j0);
        for (int k = 0; k < kmax; k++) {
            int packed = __shfl_sync(F, myp, k);
            int c = packed >> 1;
            float2 d2c = g_D2[c];
            if (packed & 1) {            // warp-uniform branch
                float w = dllr * d2c.x;
                a20 += w * g_xl[c * 64 + l];
                a21 += w * g_xl[c * 64 + l + 32];
            } else {
                float w = dhhr * d2c.y;
                a40 += w * g_xh[c * 64 + l];
                a41 += w * g_xh[c * 64 + l + 32];
            }
        }
    }
    int base = r * 64;
    g_y2[base + l] = a20; g_y2[base + l + 32] = a21;
    g_y4[base + l] = a40; g_y4[base + l + 32] = a41;
}

// ---------------- dense layer 1 (register-tiled GEMM) ----------------------
#define D1_SMEM_FLOATS (4 * 4096 + 2 * 128 * 33)
__global__ void __launch_bounds__(256, 2) k_dense1(const float* __restrict__ x,
                                                   const float* __restrict__ W1l,
                                                   const float* __restrict__ W1r,
                                                   const float* __restrict__ W3l,
                                                   const float* __restrict__ W3r,
                                                   int n) {
    extern __shared__ float s[];
    float* sw1l = s;
    float* sw1r = s + 4096;
    float* sw3l = s + 8192;
    float* sw3r = s + 12288;
    float* bufA = s + 16384;
    float* bufB = s + 16384 + 128 * 33;

    int tid = threadIdx.x;
    {
        float4* d4 = (float4*)s;
        for (int i = tid; i < 4096; i += 256) {
            const float* srcm = (i < 1024) ? W1l : (i < 2048) ? W1r : (i < 3072) ? W3l : W3r;
            d4[i] = ((const float4*)srcm)[i & 1023];
        }
    }

    int tn = tid & 7;
    int tm = tid >> 3;
    int nbase = blockIdx.x * 128;

    float accL[4][8], accH[4][8];
#pragma unroll
    for (int i = 0; i < 4; i++)
#pragma unroll
        for (int j = 0; j < 8; j++) { accL[i][j] = 0.f; accH[i][j] = 0.f; }

    for (int c = 0; c < 2; c++) {
        __syncthreads();
        for (int it = tid; it < 1024; it += 256) {
            int nl = it >> 3, f4 = it & 7;
            int node = nbase + nl;
            int kg = c * 32 + f4 * 4;
            float4 xv = make_float4(0.f, 0.f, 0.f, 0.f), y1v = xv, y3v = xv;
            float dl2 = 0.f, dh2 = 0.f;
            if (node < n) {
                xv  = __ldg((const float4*)(x + node * 64 + kg));
                y1v = *((const float4*)(g_y1 + node * 64 + kg));
                y3v = *((const float4*)(g_y3 + node * 64 + kg));
                float2 d = g_D1[node];
                dl2 = d.x * d.x; dh2 = d.y * d.y;
            }
            int sb = nl * 33 + f4 * 4;
            bufA[sb + 0] = y1v.x + dl2 * xv.x;
            bufA[sb + 1] = y1v.y + dl2 * xv.y;
            bufA[sb + 2] = y1v.z + dl2 * xv.z;
            bufA[sb + 3] = y1v.w + dl2 * xv.w;
            bufB[sb + 0] = y3v.x + dh2 * xv.x;
            bufB[sb + 1] = y3v.y + dh2 * xv.y;
            bufB[sb + 2] = y3v.z + dh2 * xv.z;
            bufB[sb + 3] = y3v.w + dh2 * xv.w;
        }
        __syncthreads();
        const float* wl = sw1l + c * 32 * 64;
        const float* wh = sw3l + c * 32 * 64;
#pragma unroll 8
        for (int k = 0; k < 32; k++) {
            float a1[4], a3[4];
#pragma unroll
            for (int i = 0; i < 4; i++) {
                a1[i] = bufA[(tm * 4 + i) * 33 + k];
                a3[i] = bufB[(tm * 4 + i) * 33 + k];
            }
            float4 l0 = *(const float4*)(wl + k * 64 + tn * 8);
            float4 l1 = *(const float4*)(wl + k * 64 + tn * 8 + 4);
            float4 h0 = *(const float4*)(wh + k * 64 + tn * 8);
            float4 h1 = *(const float4*)(wh + k * 64 + tn * 8 + 4);
#pragma unroll
            for (int i = 0; i < 4; i++) {
                accL[i][0] += a1[i] * l0.x; accL[i][1] += a1[i] * l0.y;
                accL[i][2] += a1[i] * l0.z; accL[i][3] += a1[i] * l0.w;
                accL[i][4] += a1[i] * l1.x; accL[i][5] += a1[i] * l1.y;
                accL[i][6] += a1[i] * l1.z; accL[i][7] += a1[i] * l1.w;
                accH[i][0] += a3[i] * h0.x; accH[i][1] += a3[i] * h0.y;
                accH[i][2] += a3[i] * h0.z; accH[i][3] += a3[i] * h0.w;
                accH[i][4] += a3[i] * h1.x; accH[i][5] += a3[i] * h1.y;
                accH[i][6] += a3[i] * h1.z; accH[i][7] += a3[i] * h1.w;
            }
        }
    }

    for (int c = 0; c < 2; c++) {
        __syncthreads();
        for (int it = tid; it < 1024; it += 256) {
            int nl = it >> 3, f4 = it & 7;
            int node = nbase + nl;
            int kg = c * 32 + f4 * 4;
            float4 xv = make_float4(0.f, 0.f, 0.f, 0.f);
            if (node < n) xv = __ldg((const float4*)(x + node * 64 + kg));
            int sb = nl * 33 + f4 * 4;
            bufA[sb + 0] = xv.x; bufA[sb + 1] = xv.y;
            bufA[sb + 2] = xv.z; bufA[sb + 3] = xv.w;
        }
        __syncthreads();
        const float* wl = sw1r + c * 32 * 64;
        const float* wh = sw3r + c * 32 * 64;
#pragma unroll 8
        for (int k = 0; k < 32; k++) {
            float a[4];
#pragma unroll
            for (int i = 0; i < 4; i++) a[i] = bufA[(tm * 4 + i) * 33 + k];
            float4 l0 = *(const float4*)(wl + k * 64 + tn * 8);
            float4 l1 = *(const float4*)(wl + k * 64 + tn * 8 + 4);
            float4 h0 = *(const float4*)(wh + k * 64 + tn * 8);
            float4 h1 = *(const float4*)(wh + k * 64 + tn * 8 + 4);
#pragma unroll
            for (int i = 0; i < 4; i++) {
                accL[i][0] += a[i] * l0.x; accL[i][1] += a[i] * l0.y;
                accL[i][2] += a[i] * l0.z; accL[i][3] += a[i] * l0.w;
                accL[i][4] += a[i] * l1.x; accL[i][5] += a[i] * l1.y;
                accL[i][6] += a[i] * l1.z; accL[i][7] += a[i] * l1.w;
                accH[i][0] += a[i] * h0.x; accH[i][1] += a[i] * h0.y;
                accH[i][2] += a[i] * h0.z; accH[i][3] += a[i] * h0.w;
                accH[i][4] += a[i] * h1.x; accH[i][5] += a[i] * h1.y;
                accH[i][6] += a[i] * h1.z; accH[i][7] += a[i] * h1.w;
            }
        }
    }

#pragma unroll
    for (int i = 0; i < 4; i++) {
        int node = nbase + tm * 4 + i;
        if (node >= n) continue;
        float4 v0, v1;
        v0.x = fmaxf(accL[i][0], 0.f); v0.y = fmaxf(accL[i][1], 0.f);
        v0.z = fmaxf(accL[i][2], 0.f); v0.w = fmaxf(accL[i][3], 0.f);
        v1.x = fmaxf(accL[i][4], 0.f); v1.y = fmaxf(accL[i][5], 0.f);
        v1.z = fmaxf(accL[i][6], 0.f); v1.w = fmaxf(accL[i][7], 0.f);
        *((float4*)(g_xl + node * 64 + tn * 8))     = v0;
        *((float4*)(g_xl + node * 64 + tn * 8 + 4)) = v1;
        v0.x = fmaxf(accH[i][0], 0.f); v0.y = fmaxf(accH[i][1], 0.f);
        v0.z = fmaxf(accH[i][2], 0.f); v0.w = fmaxf(accH[i][3], 0.f);
        v1.x = fmaxf(accH[i][4], 0.f); v1.y = fmaxf(accH[i][5], 0.f);
        v1.z = fmaxf(accH[i][6], 0.f); v1.w = fmaxf(accH[i][7], 0.f);
        *((float4*)(g_xh + node * 64 + tn * 8))     = v0;
        *((float4*)(g_xh + node * 64 + tn * 8 + 4)) = v1;
    }
}

// ---------------- dense layer 2 GEMM + mix (register-tiled) ----------------
#define D2_SMEM_FLOATS (5 * 4096 + 2 * 64 * 33)
__global__ void __launch_bounds__(256, 2) k_dense2(const float* __restrict__ x,
                                                   const int* __restrict__ cc,
                                                   const float* __restrict__ W2l,
                                                   const float* __restrict__ W2r,
                                                   const float* __restrict__ W4l,
                                                   const float* __restrict__ W4r,
                                                   const float* __restrict__ WX,
                                                   const float* __restrict__ lam1,
                                                   const float* __restrict__ lam2,
                                                   int n) {
    extern __shared__ float s[];
    float* sw2l = s;
    float* sw2r = s + 4096;
    float* sw4l = s + 8192;
    float* sw4r = s + 12288;
    float* swx  = s + 16384;
    float* bufA = s + 20480;
    float* bufB = s + 20480 + 64 * 33;

    int tid = threadIdx.x;
    {
        float4* d4 = (float4*)s;
        for (int i = tid; i < 5120; i += 256) {
            const float* srcm = (i < 1024) ? W2l : (i < 2048) ? W2r :
                                (i < 3072) ? W4l : (i < 4096) ? W4r : WX;
            d4[i] = ((const float4*)srcm)[i & 1023];
        }
    }

    int tn = tid & 15;
    int tm = tid >> 4;
    int nbase = blockIdx.x * 64;

    float accZ2[4][4], accZ4[4][4], accM[4][4];
#pragma unroll
    for (int i = 0; i < 4; i++)
#pragma unroll
        for (int j = 0; j < 4; j++) { accZ2[i][j] = 0.f; accZ4[i][j] = 0.f; accM[i][j] = 0.f; }

    for (int c = 0; c < 2; c++) {
        __syncthreads();
        for (int it = tid; it < 512; it += 256) {
            int nl = it >> 3, f4 = it & 7;
            int node = nbase + nl;
            int kg = c * 32 + f4 * 4;
            float4 xlv = make_float4(0.f, 0.f, 0.f, 0.f), xhv = xlv, y2v = xlv, y4v = xlv;
            float dll2 = 0.f, dhh2 = 0.f;
            if (node < n) {
                xlv = *((const float4*)(g_xl + node * 64 + kg));
                xhv = *((const float4*)(g_xh + node * 64 + kg));
                y2v = *((const float4*)(g_y2 + node * 64 + kg));
                y4v = *((const float4*)(g_y4 + node * 64 + kg));
                float2 d = g_D2[node];
                dll2 = d.x * d.x; dhh2 = d.y * d.y;
            }
            int sb = nl * 33 + f4 * 4;
            bufA[sb + 0] = y2v.x + dll2 * xlv.x;
            bufA[sb + 1] = y2v.y + dll2 * xlv.y;
            bufA[sb + 2] = y2v.z + dll2 * xlv.z;
            bufA[sb + 3] = y2v.w + dll2 * xlv.w;
            bufB[sb + 0] = y4v.x + dhh2 * xhv.x;
            bufB[sb + 1] = y4v.y + dhh2 * xhv.y;
            bufB[sb + 2] = y4v.z + dhh2 * xhv.z;
            bufB[sb + 3] = y4v.w + dhh2 * xhv.w;
        }
        __syncthreads();
        const float* w2 = sw2l + c * 32 * 64;
        const float* w4 = sw4l + c * 32 * 64;
#pragma unroll 8
        for (int k = 0; k < 32; k++) {
            float a2[4], a4[4];
#pragma unroll
            for (int i = 0; i < 4; i++) {
                a2[i] = bufA[(tm * 4 + i) * 33 + k];
                a4[i] = bufB[(tm * 4 + i) * 33 + k];
            }
            float4 wz2 = *(const float4*)(w2 + k * 64 + tn * 4);
            float4 wz4 = *(const float4*)(w4 + k * 64 + tn * 4);
#pragma unroll
            for (int i = 0; i < 4; i++) {
                accZ2[i][0] += a2[i] * wz2.x; accZ2[i][1] += a2[i] * wz2.y;
                accZ2[i][2] += a2[i] * wz2.z; accZ2[i][3] += a2[i] * wz2.w;
                accZ4[i][0] += a4[i] * wz4.x; accZ4[i][1] += a4[i] * wz4.y;
                accZ4[i][2] += a4[i] * wz4.z; accZ4[i][3] += a4[i] * wz4.w;
            }
        }
    }

    for (int c = 0; c < 2; c++) {
        __syncthreads();
        for (int it = tid; it < 512; it += 256) {
            int nl = it >> 3, f4 = it & 7;
            int node = nbase + nl;
            int kg = c * 32 + f4 * 4;
            float4 xlv = make_float4(0.f, 0.f, 0.f, 0.f), xhv = xlv;
            if (node < n) {
                xlv = *((const float4*)(g_xl + node * 64 + kg));
                xhv = *((const float4*)(g_xh + node * 64 + kg));
            }
            int sb = nl * 33 + f4 * 4;
            bufA[sb + 0] = xlv.x; bufA[sb + 1] = xlv.y;
            bufA[sb + 2] = xlv.z; bufA[sb + 3] = xlv.w;
            bufB[sb + 0] = xhv.x; bufB[sb + 1] = xhv.y;
            bufB[sb + 2] = xhv.z; bufB[sb + 3] = xhv.w;
        }
        __syncthreads();
        const float* w2 = sw2r + c * 32 * 64;
        const float* w4 = sw4r + c * 32 * 64;
#pragma unroll 8
        for (int k = 0; k < 32; k++) {
            float a2[4], a4[4];
#pragma unroll
            for (int i = 0; i < 4; i++) {
                a2[i] = bufA[(tm * 4 + i) * 33 + k];
                a4[i] = bufB[(tm * 4 + i) * 33 + k];
            }
            float4 wz2 = *(const float4*)(w2 + k * 64 + tn * 4);
            float4 wz4 = *(const float4*)(w4 + k * 64 + tn * 4);
#pragma unroll
            for (int i = 0; i < 4; i++) {
                accZ2[i][0] += a2[i] * wz2.x; accZ2[i][1] += a2[i] * wz2.y;
                accZ2[i][2] += a2[i] * wz2.z; accZ2[i][3] += a2[i] * wz2.w;
                accZ4[i][0] += a4[i] * wz4.x; accZ4[i][1] += a4[i] * wz4.y;
                accZ4[i][2] += a4[i] * wz4.z; accZ4[i][3] += a4[i] * wz4.w;
            }
        }
    }

    for (int c = 0; c < 2; c++) {
        __syncthreads();
        for (int it = tid; it < 512; it += 256) {
            int nl = it >> 3, f4 = it & 7;
            int node = nbase + nl;
            int kg = c * 32 + f4 * 4;
            float4 xv = make_float4(0.f, 0.f, 0.f, 0.f);
            if (node < n) xv = __ldg((const float4*)(x + node * 64 + kg));
            int sb = nl * 33 + f4 * 4;
            bufA[sb + 0] = xv.x; bufA[sb + 1] = xv.y;
            bufA[sb + 2] = xv.z; bufA[sb + 3] = xv.w;
        }
        __syncthreads();
        const float* wm = swx + c * 32 * 64;
#pragma unroll 8
        for (int k = 0; k < 32; k++) {
            float a[4];
#pragma unroll
            for (int i = 0; i < 4; i++) a[i] = bufA[(tm * 4 + i) * 33 + k];
            float4 wv = *(const float4*)(wm + k * 64 + tn * 4);
#pragma unroll
            for (int i = 0; i < 4; i++) {
                accM[i][0] += a[i] * wv.x; accM[i][1] += a[i] * wv.y;
                accM[i][2] += a[i] * wv.z; accM[i][3] += a[i] * wv.w;
            }
        }
    }

    float e0 = __expf(lam1[0]), e1 = __expf(lam1[1]);
    float lamxl = e0 / (e0 + e1), laml = e1 / (e0 + e1);
    float f0 = __expf(lam2[0]), f1 = __expf(lam2[1]);
    float lamxh = f0 / (f0 + f1), lamh = f1 / (f0 + f1);

#pragma unroll
    for (int i = 0; i < 4; i++) {
        int node = nbase + tm * 4 + i;
        if (node >= n) continue;
        float lamx = __ldg(cc + node) ? lamxl : lamxh;
        float4 v;
        v.x = fmaxf(lamx * accM[i][0] + laml * accZ2[i][0] + lamh * accZ4[i][0], 0.f);
        v.y = fmaxf(lamx * accM[i][1] + laml * accZ2[i][1] + lamh * accZ4[i][1], 0.f);
        v.z = fmaxf(lamx * accM[i][2] + laml * accZ2[i][2] + lamh * accZ4[i][2], 0.f);
        v.w = fmaxf(lamx * accM[i][3] + laml * accZ2[i][3] + lamh * accZ4[i][3], 0.f);
        *((float4*)(g_xl + node * 64 + tn * 4)) = v;
    }
}

// ---------------- classifier: out = xf @ linW + linB -----------------------
__global__ void __launch_bounds__(256) k_cls(const float* __restrict__ linW,
                                             const float* __restrict__ linB,
                                             float* __restrict__ out, int n) {
    __shared__ float slin[2560];
    __shared__ float slinb[40];
    int tid = threadIdx.x;
    for (int i = tid; i < 2560; i += 256) slin[i] = linW[i];
    if (tid < 40) slinb[tid] = linB[tid];
    __syncthreads();

    int warp = tid >> 5, l = tid & 31;
    int node = blockIdx.x * 8 + warp;
    if (node >= n) return;
    int base = node * 64;
    float xf0 = g_xl[base + l], xf1 = g_xl[base + l + 32];

    float acc0 = slinb[l];
    float acc1 = (l < 8) ? slinb[32 + l] : 0.f;
    const unsigned m = 0xffffffffu;
#pragma unroll
    for (int k = 0; k < 32; k++) {
        float b = __shfl_sync(m, xf0, k);
        acc0 += b * slin[k * 40 + l];
        if (l < 8) acc1 += b * slin[k * 40 + 32 + l];
    }
#pragma unroll
    for (int k = 0; k < 32; k++) {
        float b = __shfl_sync(m, xf1, k);
        int o = (k + 32) * 40;
        acc0 += b * slin[o + l];
        if (l < 8) acc1 += b * slin[o + 32 + l];
    }
    out[node * 40 + l] = acc0;
    if (l < 8) out[node * 40 + 32 + l] = acc1;
}

// ---------------- host launcher --------------------------------------------
extern "C" void kernel_launch(void* const* d_in, const int* in_sizes, int n_in,
                              void* d_out, int out_size) {
    const float* x    = (const float*)d_in[0];
    const int*   ei   = (const int*)d_in[1];
    const int*   cc   = (const int*)d_in[2];
    const float* W1l  = (const float*)d_in[3];
    const float* W1r  = (const float*)d_in[4];
    const float* W2l  = (const float*)d_in[5];
    const float* W2r  = (const float*)d_in[6];
    const float* W3l  = (const float*)d_in[7];
    const float* W3r  = (const float*)d_in[8];
    const float* W4l  = (const float*)d_in[9];
    const float* W4r  = (const float*)d_in[10];
    const float* WX   = (const float*)d_in[11];
    const float* lam1 = (const float*)d_in[12];
    const float* lam2 = (const float*)d_in[13];
    const float* linW = (const float*)d_in[14];
    const float* linB = (const float*)d_in[15];
    float* out = (float*)d_out;

    int n = in_sizes[0] / 64;
    int E = in_sizes[1] / 2;
    const int* col = ei;
    const int* row = ei + E;
    int nblk = (n + 1023) / 1024;   // scan blocks (<=128)

    cudaFuncSetAttribute(k_dense1, cudaFuncAttributeMaxDynamicSharedMemorySize,
                         D1_SMEM_FLOATS * 4);
    cudaFuncSetAttribute(k_dense2, cudaFuncAttributeMaxDynamicSharedMemorySize,
                         D2_SMEM_FLOATS * 4);

    k_zero_small<<<(n + 255) / 256, 256>>>(n);
    k_deg<<<(E + 255) / 256, 256>>>(col, row, cc, E);
    k_scanA<<<nblk, 1024>>>(n);
    k_scanB<<<1, 128>>>(nblk);
    k_scanC<<<nblk, 1024>>>(cc, n);
    k_scatter<<<(E + 255) / 256, 256>>>(col, row, cc, E);
    k_gather0<<<(n + 7) / 8, 256>>>(cc, x, n);
    k_dense1<<<(n + 127) / 128, 256, D1_SMEM_FLOATS * 4>>>(x, W1l, W1r, W3l, W3r, n);
    k_gather1<<<(n + 7) / 8, 256>>>(n);
    k_dense2<<<(n + 63) / 64, 256, D2_SMEM_FLOATS * 4>>>(x, cc, W2l, W2r, W4l, W4r,
                                                         WX, lam1, lam2, n);
    k_cls<<<(n + 7) / 8, 256>>>(linW, linB, out, n);
}

// round 4
// speedup vs baseline: 2.3299x; 1.1415x over previous
#include <cuda_runtime.h>

#define NMAX 100000
#define EMAX 1600000

// ---------------- scratch (device globals; no allocation allowed) ----------
__device__ float g_y1[NMAX * 64];
__device__ float g_y2[NMAX * 64];
__device__ float g_y3[NMAX * 64];
__device__ float g_y4[NMAX * 64];
__device__ float g_xl[NMAX * 64];
__device__ float g_xh[NMAX * 64];
__device__ float2 g_D1[NMAX];
__device__ float2 g_D2[NMAX];
__device__ int    g_cnt[NMAX];   // packed (deg<<16)|s during build; decoded deg after scanC
__device__ int    g_ptr[NMAX];
__device__ int    g_pos[NMAX];
__device__ int    g_adj[EMAX];
__device__ int    g_bsum[128];
__device__ int    g_boff[128];

// ---------------- tiny zero -------------------------------------------------
__global__ void k_zero_small(int n) {
    int i = blockIdx.x * blockDim.x + threadIdx.x;
    if (i < n) g_cnt[i] = 0;
}

// ---------------- degree pass (packed single atomic per edge) ---------------
__global__ void k_deg(const int* __restrict__ col, const int* __restrict__ row,
                      const int* __restrict__ cc, int E) {
    int e = blockIdx.x * blockDim.x + threadIdx.x;
    if (e >= E) return;
    int r = __ldg(row + e);
    int c = __ldg(col + e);
    if (r == c) return;
    atomicAdd(&g_cnt[r], 0x10000 | __ldg(cc + c));
}

// ---------------- scan kernel A: per-1024-chunk sums of deg -----------------
__global__ void k_scanA(int n) {
    __shared__ int sm[1024];
    int tid = threadIdx.x;
    int i = blockIdx.x * 1024 + tid;
    int v = (i < n) ? (g_cnt[i] >> 16) : 0;
    sm[tid] = v;
    __syncthreads();
    for (int off = 512; off; off >>= 1) {
        if (tid < off) sm[tid] += sm[tid + off];
        __syncthreads();
    }
    if (tid == 0) g_bsum[blockIdx.x] = sm[0];
}

// ---------------- scan kernel B: exclusive scan of block sums ---------------
__global__ void k_scanB(int nb) {
    int t = threadIdx.x;                 // 128 threads
    int lane = t & 31, w = t >> 5;
    int v = (t < nb) ? g_bsum[t] : 0;
    int xv = v;
    const unsigned F = 0xffffffffu;
#pragma unroll
    for (int o = 1; o < 32; o <<= 1) {
        int y = __shfl_up_sync(F, xv, o);
        if (lane >= o) xv += y;
    }
    __shared__ int ws[4];
    if (lane == 31) ws[w] = xv;
    __syncthreads();
    __shared__ int wo[4];
    if (t == 0) {
        int a = 0;
        for (int i = 0; i < 4; i++) { wo[i] = a; a += ws[i]; }
    }
    __syncthreads();
    if (t < 128) g_boff[t] = xv + wo[w] - v;
}

// ---------------- scan kernel C: ptr/pos + coefficients + decode deg --------
__global__ void k_scanC(const int* __restrict__ cc, int n) {
    __shared__ int ws[32];
    int tid = threadIdx.x;
    int lane = tid & 31, w = tid >> 5;
    int i = blockIdx.x * 1024 + tid;
    int packed = (i < n) ? g_cnt[i] : 0;
    int v = packed >> 16;
    int xv = v;
    const unsigned F = 0xffffffffu;
#pragma unroll
    for (int o = 1; o < 32; o <<= 1) {
        int y = __shfl_up_sync(F, xv, o);
        if (lane >= o) xv += y;
    }
    if (lane == 31) ws[w] = xv;
    __syncthreads();
    if (w == 0) {
        int t2 = ws[lane];
        int sv = t2;
#pragma unroll
        for (int o = 1; o < 32; o <<= 1) {
            int y = __shfl_up_sync(F, sv, o);
            if (lane >= o) sv += y;
        }
        ws[lane] = sv - t2;
    }
    __syncthreads();
    if (i < n) {
        int ptr = g_boff[blockIdx.x] + ws[w] + xv - v;
        g_ptr[i] = ptr;
        g_pos[i] = ptr;
        g_cnt[i] = v;                          // decoded degree for gathers
        float cnt = (float)v;
        float sv2 = (float)(packed & 0xffff);
        int cci = __ldg(cc + i);
        float dl  = rsqrtf((cci ? cnt : 0.f) + 1.f);
        float dh  = rsqrtf((cci ? 0.f : cnt) + 1.f);
        float dll = rsqrtf(sv2 + 1.f);
        float dhh = rsqrtf(cnt - sv2 + 1.f);
        g_D1[i] = make_float2(dl, dh);
        g_D2[i] = make_float2(dll, dhh);
    }
}

// ---------------- scatter: build adjacency ----------------------------------
__global__ void k_scatter(const int* __restrict__ col, const int* __restrict__ row,
                          const int* __restrict__ cc, int E) {
    int e = blockIdx.x * blockDim.x + threadIdx.x;
    if (e >= E) return;
    int r = __ldg(row + e);
    int c = __ldg(col + e);
    if (r == c) return;
    int p = atomicAdd(&g_pos[r], 1);
    g_adj[p] = (c << 1) | __ldg(cc + c);
}

// ---------------- gather pass 0: half-warp per neighbor, float4 lanes -------
__global__ void __launch_bounds__(256) k_gather0(const int* __restrict__ cc,
                                                 const float* __restrict__ x,
                                                 int n) {
    int tid = threadIdx.x;
    int warp = tid >> 5, l = tid & 31;
    int r = blockIdx.x * 8 + warp;
    if (r >= n) return;
    int half = l >> 4, q = l & 15;

    int ccr = __ldg(cc + r);
    float2 d1r = g_D1[r];
    float drv = ccr ? d1r.x : d1r.y;
    int start = g_ptr[r];
    int deg = g_cnt[r];

    float4 acc = make_float4(0.f, 0.f, 0.f, 0.f);
    const unsigned F = 0xffffffffu;
    for (int j0 = 0; j0 < deg; j0 += 32) {
        int myp = 0;
        if (j0 + l < deg) myp = __ldg(g_adj + start + j0 + l);
        int kmax = deg - j0; if (kmax > 32) kmax = 32;
        int pairs = (kmax + 1) >> 1;
        for (int k = 0; k < pairs; k++) {
            int idx = 2 * k + half;
            int packed = __shfl_sync(F, myp, idx);
            int c = packed >> 1;
            float2 d1c = __ldg(&g_D1[c]);
            float w = drv * (ccr ? d1c.x : d1c.y);
            if (idx >= kmax) w = 0.f;
            float4 v = __ldg((const float4*)(x + c * 64) + q);
            acc.x += w * v.x; acc.y += w * v.y;
            acc.z += w * v.z; acc.w += w * v.w;
        }
    }
    acc.x += __shfl_xor_sync(F, acc.x, 16);
    acc.y += __shfl_xor_sync(F, acc.y, 16);
    acc.z += __shfl_xor_sync(F, acc.z, 16);
    acc.w += __shfl_xor_sync(F, acc.w, 16);
    if (half == 0) {
        float4 z = make_float4(0.f, 0.f, 0.f, 0.f);
        float4* y1 = (float4*)(g_y1 + r * 64) + q;
        float4* y3 = (float4*)(g_y3 + r * 64) + q;
        if (ccr) { *y1 = acc; *y3 = z; }
        else     { *y3 = acc; *y1 = z; }
    }
}

// ---------------- gather pass 1: per-neighbor channel (predicated) ----------
__global__ void __launch_bounds__(256) k_gather1(int n) {
    int tid = threadIdx.x;
    int warp = tid >> 5, l = tid & 31;
    int r = blockIdx.x * 8 + warp;
    if (r >= n) return;
    int half = l >> 4, q = l & 15;

    float2 d2r = g_D2[r];
    float dllr = d2r.x, dhhr = d2r.y;
    int start = g_ptr[r];
    int deg = g_cnt[r];

    float4 a2 = make_float4(0.f, 0.f, 0.f, 0.f);
    float4 a4 = make_float4(0.f, 0.f, 0.f, 0.f);
    const unsigned F = 0xffffffffu;
    for (int j0 = 0; j0 < deg; j0 += 32) {
        int myp = 0;
        if (j0 + l < deg) myp = __ldg(g_adj + start + j0 + l);
        int kmax = deg - j0; if (kmax > 32) kmax = 32;
        int pairs = (kmax + 1) >> 1;
        for (int k = 0; k < pairs; k++) {
            int idx = 2 * k + half;
            int packed = __shfl_sync(F, myp, idx);
            int c = packed >> 1;
            int sel = packed & 1;
            float2 d2c = __ldg(&g_D2[c]);
            float w2 = sel ? dllr * d2c.x : 0.f;
            float w4 = sel ? 0.f : dhhr * d2c.y;
            if (idx >= kmax) { w2 = 0.f; w4 = 0.f; }
            const float* src = sel ? g_xl : g_xh;
            float4 v = __ldg((const float4*)(src + c * 64) + q);
            a2.x += w2 * v.x; a2.y += w2 * v.y; a2.z += w2 * v.z; a2.w += w2 * v.w;
            a4.x += w4 * v.x; a4.y += w4 * v.y; a4.z += w4 * v.z; a4.w += w4 * v.w;
        }
    }
    a2.x += __shfl_xor_sync(F, a2.x, 16);
    a2.y += __shfl_xor_sync(F, a2.y, 16);
    a2.z += __shfl_xor_sync(F, a2.z, 16);
    a2.w += __shfl_xor_sync(F, a2.w, 16);
    a4.x += __shfl_xor_sync(F, a4.x, 16);
    a4.y += __shfl_xor_sync(F, a4.y, 16);
    a4.z += __shfl_xor_sync(F, a4.z, 16);
    a4.w += __shfl_xor_sync(F, a4.w, 16);
    if (half == 0) {
        *((float4*)(g_y2 + r * 64) + q) = a2;
        *((float4*)(g_y4 + r * 64) + q) = a4;
    }
}

// ---------------- dense layer 1 (register-tiled GEMM) ----------------------
#define D1_SMEM_FLOATS (4 * 4096 + 2 * 128 * 33)
__global__ void __launch_bounds__(256, 2) k_dense1(const float* __restrict__ x,
                                                   const float* __restrict__ W1l,
                                                   const float* __restrict__ W1r,
                                                   const float* __restrict__ W3l,
                                                   const float* __restrict__ W3r,
                                                   int n) {
    extern __shared__ float s[];
    float* sw1l = s;
    float* sw1r = s + 4096;
    float* sw3l = s + 8192;
    float* sw3r = s + 12288;
    float* bufA = s + 16384;
    float* bufB = s + 16384 + 128 * 33;

    int tid = threadIdx.x;
    {
        float4* d4 = (float4*)s;
        for (int i = tid; i < 4096; i += 256) {
            const float* srcm = (i < 1024) ? W1l : (i < 2048) ? W1r : (i < 3072) ? W3l : W3r;
            d4[i] = ((const float4*)srcm)[i & 1023];
        }
    }

    int tn = tid & 7;
    int tm = tid >> 3;
    int nbase = blockIdx.x * 128;

    float accL[4][8], accH[4][8];
#pragma unroll
    for (int i = 0; i < 4; i++)
#pragma unroll
        for (int j = 0; j < 8; j++) { accL[i][j] = 0.f; accH[i][j] = 0.f; }

    for (int c = 0; c < 2; c++) {
        __syncthreads();
        for (int it = tid; it < 1024; it += 256) {
            int nl = it >> 3, f4 = it & 7;
            int node = nbase + nl;
            int kg = c * 32 + f4 * 4;
            float4 xv = make_float4(0.f, 0.f, 0.f, 0.f), y1v = xv, y3v = xv;
            float dl2 = 0.f, dh2 = 0.f;
            if (node < n) {
                xv  = __ldg((const float4*)(x + node * 64 + kg));
                y1v = *((const float4*)(g_y1 + node * 64 + kg));
                y3v = *((const float4*)(g_y3 + node * 64 + kg));
                float2 d = g_D1[node];
                dl2 = d.x * d.x; dh2 = d.y * d.y;
            }
            int sb = nl * 33 + f4 * 4;
            bufA[sb + 0] = y1v.x + dl2 * xv.x;
            bufA[sb + 1] = y1v.y + dl2 * xv.y;
            bufA[sb + 2] = y1v.z + dl2 * xv.z;
            bufA[sb + 3] = y1v.w + dl2 * xv.w;
            bufB[sb + 0] = y3v.x + dh2 * xv.x;
            bufB[sb + 1] = y3v.y + dh2 * xv.y;
            bufB[sb + 2] = y3v.z + dh2 * xv.z;
            bufB[sb + 3] = y3v.w + dh2 * xv.w;
        }
        __syncthreads();
        const float* wl = sw1l + c * 32 * 64;
        const float* wh = sw3l + c * 32 * 64;
#pragma unroll 8
        for (int k = 0; k < 32; k++) {
            float a1[4], a3[4];
#pragma unroll
            for (int i = 0; i < 4; i++) {
                a1[i] = bufA[(tm * 4 + i) * 33 + k];
                a3[i] = bufB[(tm * 4 + i) * 33 + k];
            }
            float4 l0 = *(const float4*)(wl + k * 64 + tn * 8);
            float4 l1 = *(const float4*)(wl + k * 64 + tn * 8 + 4);
            float4 h0 = *(const float4*)(wh + k * 64 + tn * 8);
            float4 h1 = *(const float4*)(wh + k * 64 + tn * 8 + 4);
#pragma unroll
            for (int i = 0; i < 4; i++) {
                accL[i][0] += a1[i] * l0.x; accL[i][1] += a1[i] * l0.y;
                accL[i][2] += a1[i] * l0.z; accL[i][3] += a1[i] * l0.w;
                accL[i][4] += a1[i] * l1.x; accL[i][5] += a1[i] * l1.y;
                accL[i][6] += a1[i] * l1.z; accL[i][7] += a1[i] * l1.w;
                accH[i][0] += a3[i] * h0.x; accH[i][1] += a3[i] * h0.y;
                accH[i][2] += a3[i] * h0.z; accH[i][3] += a3[i] * h0.w;
                accH[i][4] += a3[i] * h1.x; accH[i][5] += a3[i] * h1.y;
                accH[i][6] += a3[i] * h1.z; accH[i][7] += a3[i] * h1.w;
            }
        }
    }

    for (int c = 0; c < 2; c++) {
        __syncthreads();
        for (int it = tid; it < 1024; it += 256) {
            int nl = it >> 3, f4 = it & 7;
            int node = nbase + nl;
            int kg = c * 32 + f4 * 4;
            float4 xv = make_float4(0.f, 0.f, 0.f, 0.f);
            if (node < n) xv = __ldg((const float4*)(x + node * 64 + kg));
            int sb = nl * 33 + f4 * 4;
            bufA[sb + 0] = xv.x; bufA[sb + 1] = xv.y;
            bufA[sb + 2] = xv.z; bufA[sb + 3] = xv.w;
        }
        __syncthreads();
        const float* wl = sw1r + c * 32 * 64;
        const float* wh = sw3r + c * 32 * 64;
#pragma unroll 8
        for (int k = 0; k < 32; k++) {
            float a[4];
#pragma unroll
            for (int i = 0; i < 4; i++) a[i] = bufA[(tm * 4 + i) * 33 + k];
            float4 l0 = *(const float4*)(wl + k * 64 + tn * 8);
            float4 l1 = *(const float4*)(wl + k * 64 + tn * 8 + 4);
            float4 h0 = *(const float4*)(wh + k * 64 + tn * 8);
            float4 h1 = *(const float4*)(wh + k * 64 + tn * 8 + 4);
#pragma unroll
            for (int i = 0; i < 4; i++) {
                accL[i][0] += a[i] * l0.x; accL[i][1] += a[i] * l0.y;
                accL[i][2] += a[i] * l0.z; accL[i][3] += a[i] * l0.w;
                accL[i][4] += a[i] * l1.x; accL[i][5] += a[i] * l1.y;
                accL[i][6] += a[i] * l1.z; accL[i][7] += a[i] * l1.w;
                accH[i][0] += a[i] * h0.x; accH[i][1] += a[i] * h0.y;
                accH[i][2] += a[i] * h0.z; accH[i][3] += a[i] * h0.w;
                accH[i][4] += a[i] * h1.x; accH[i][5] += a[i] * h1.y;
                accH[i][6] += a[i] * h1.z; accH[i][7] += a[i] * h1.w;
            }
        }
    }

#pragma unroll
    for (int i = 0; i < 4; i++) {
        int node = nbase + tm * 4 + i;
        if (node >= n) continue;
        float4 v0, v1;
        v0.x = fmaxf(accL[i][0], 0.f); v0.y = fmaxf(accL[i][1], 0.f);
        v0.z = fmaxf(accL[i][2], 0.f); v0.w = fmaxf(accL[i][3], 0.f);
        v1.x = fmaxf(accL[i][4], 0.f); v1.y = fmaxf(accL[i][5], 0.f);
        v1.z = fmaxf(accL[i][6], 0.f); v1.w = fmaxf(accL[i][7], 0.f);
        *((float4*)(g_xl + node * 64 + tn * 8))     = v0;
        *((float4*)(g_xl + node * 64 + tn * 8 + 4)) = v1;
        v0.x = fmaxf(accH[i][0], 0.f); v0.y = fmaxf(accH[i][1], 0.f);
        v0.z = fmaxf(accH[i][2], 0.f); v0.w = fmaxf(accH[i][3], 0.f);
        v1.x = fmaxf(accH[i][4], 0.f); v1.y = fmaxf(accH[i][5], 0.f);
        v1.z = fmaxf(accH[i][6], 0.f); v1.w = fmaxf(accH[i][7], 0.f);
        *((float4*)(g_xh + node * 64 + tn * 8))     = v0;
        *((float4*)(g_xh + node * 64 + tn * 8 + 4)) = v1;
    }
}

// ---------------- dense layer 2 GEMM + mix + FUSED classifier ---------------
// smem: W2l W2r W4l W4r WX (20480) + buf (4224, reused as xf stage)
//       + linW (2560) + linB (40)
#define D2_SMEM_FLOATS (5 * 4096 + 2 * 64 * 33 + 2560 + 40)
__global__ void __launch_bounds__(256, 2) k_dense2(const float* __restrict__ x,
                                                   const int* __restrict__ cc,
                                                   const float* __restrict__ W2l,
                                                   const float* __restrict__ W2r,
                                                   const float* __restrict__ W4l,
                                                   const float* __restrict__ W4r,
                                                   const float* __restrict__ WX,
                                                   const float* __restrict__ lam1,
                                                   const float* __restrict__ lam2,
                                                   const float* __restrict__ linW,
                                                   const float* __restrict__ linB,
                                                   float* __restrict__ out, int n) {
    extern __shared__ float s[];
    float* sw2l = s;
    float* sw2r = s + 4096;
    float* sw4l = s + 8192;
    float* sw4r = s + 12288;
    float* swx  = s + 16384;
    float* bufA = s + 20480;            // 64*33
    float* bufB = s + 20480 + 64 * 33;  // 64*33
    float* sxf  = bufA;                 // reused: 64 nodes x 65 stride = 4160
    float* slin  = s + 24704;           // 2560
    float* slinb = s + 27264;           // 40

    int tid = threadIdx.x;
    {
        float4* d4 = (float4*)s;
        for (int i = tid; i < 5120; i += 256) {
            const float* srcm = (i < 1024) ? W2l : (i < 2048) ? W2r :
                                (i < 3072) ? W4l : (i < 4096) ? W4r : WX;
            d4[i] = ((const float4*)srcm)[i & 1023];
        }
        float4* l4 = (float4*)slin;
        for (int i = tid; i < 640; i += 256) l4[i] = ((const float4*)linW)[i];
        if (tid < 40) slinb[tid] = linB[tid];
    }

    int tn = tid & 15;
    int tm = tid >> 4;
    int nbase = blockIdx.x * 64;

    float accZ2[4][4], accZ4[4][4], accM[4][4];
#pragma unroll
    for (int i = 0; i < 4; i++)
#pragma unroll
        for (int j = 0; j < 4; j++) { accZ2[i][j] = 0.f; accZ4[i][j] = 0.f; accM[i][j] = 0.f; }

    for (int c = 0; c < 2; c++) {
        __syncthreads();
        for (int it = tid; it < 512; it += 256) {
            int nl = it >> 3, f4 = it & 7;
            int node = nbase + nl;
            int kg = c * 32 + f4 * 4;
            float4 xlv = make_float4(0.f, 0.f, 0.f, 0.f), xhv = xlv, y2v = xlv, y4v = xlv;
            float dll2 = 0.f, dhh2 = 0.f;
            if (node < n) {
                xlv = *((const float4*)(g_xl + node * 64 + kg));
                xhv = *((const float4*)(g_xh + node * 64 + kg));
                y2v = *((const float4*)(g_y2 + node * 64 + kg));
                y4v = *((const float4*)(g_y4 + node * 64 + kg));
                float2 d = g_D2[node];
                dll2 = d.x * d.x; dhh2 = d.y * d.y;
            }
            int sb = nl * 33 + f4 * 4;
            bufA[sb + 0] = y2v.x + dll2 * xlv.x;
            bufA[sb + 1] = y2v.y + dll2 * xlv.y;
            bufA[sb + 2] = y2v.z + dll2 * xlv.z;
            bufA[sb + 3] = y2v.w + dll2 * xlv.w;
            bufB[sb + 0] = y4v.x + dhh2 * xhv.x;
            bufB[sb + 1] = y4v.y + dhh2 * xhv.y;
            bufB[sb + 2] = y4v.z + dhh2 * xhv.z;
            bufB[sb + 3] = y4v.w + dhh2 * xhv.w;
        }
        __syncthreads();
        const float* w2 = sw2l + c * 32 * 64;
        const float* w4 = sw4l + c * 32 * 64;
#pragma unroll 8
        for (int k = 0; k < 32; k++) {
            float a2[4], a4[4];
#pragma unroll
            for (int i = 0; i < 4; i++) {
                a2[i] = bufA[(tm * 4 + i) * 33 + k];
                a4[i] = bufB[(tm * 4 + i) * 33 + k];
            }
            float4 wz2 = *(const float4*)(w2 + k * 64 + tn * 4);
            float4 wz4 = *(const float4*)(w4 + k * 64 + tn * 4);
#pragma unroll
            for (int i = 0; i < 4; i++) {
                accZ2[i][0] += a2[i] * wz2.x; accZ2[i][1] += a2[i] * wz2.y;
                accZ2[i][2] += a2[i] * wz2.z; accZ2[i][3] += a2[i] * wz2.w;
                accZ4[i][0] += a4[i] * wz4.x; accZ4[i][1] += a4[i] * wz4.y;
                accZ4[i][2] += a4[i] * wz4.z; accZ4[i][3] += a4[i] * wz4.w;
            }
        }
    }

    for (int c = 0; c < 2; c++) {
        __syncthreads();
        for (int it = tid; it < 512; it += 256) {
            int nl = it >> 3, f4 = it & 7;
            int node = nbase + nl;
            int kg = c * 32 + f4 * 4;
            float4 xlv = make_float4(0.f, 0.f, 0.f, 0.f), xhv = xlv;
            if (node < n) {
                xlv = *((const float4*)(g_xl + node * 64 + kg));
                xhv = *((const float4*)(g_xh + node * 64 + kg));
            }
            int sb = nl * 33 + f4 * 4;
            bufA[sb + 0] = xlv.x; bufA[sb + 1] = xlv.y;
            bufA[sb + 2] = xlv.z; bufA[sb + 3] = xlv.w;
            bufB[sb + 0] = xhv.x; bufB[sb + 1] = xhv.y;
            bufB[sb + 2] = xhv.z; bufB[sb + 3] = xhv.w;
        }
        __syncthreads();
        const float* w2 = sw2r + c * 32 * 64;
        const float* w4 = sw4r + c * 32 * 64;
#pragma unroll 8
        for (int k = 0; k < 32; k++) {
            float a2[4], a4[4];
#pragma unroll
            for (int i = 0; i < 4; i++) {
                a2[i] = bufA[(tm * 4 + i) * 33 + k];
                a4[i] = bufB[(tm * 4 + i) * 33 + k];
            }
            float4 wz2 = *(const float4*)(w2 + k * 64 + tn * 4);
            float4 wz4 = *(const float4*)(w4 + k * 64 + tn * 4);
#pragma unroll
            for (int i = 0; i < 4; i++) {
                accZ2[i][0] += a2[i] * wz2.x; accZ2[i][1] += a2[i] * wz2.y;
                accZ2[i][2] += a2[i] * wz2.z; accZ2[i][3] += a2[i] * wz2.w;
                accZ4[i][0] += a4[i] * wz4.x; accZ4[i][1] += a4[i] * wz4.y;
                accZ4[i][2] += a4[i] * wz4.z; accZ4[i][3] += a4[i] * wz4.w;
            }
        }
    }

    for (int c = 0; c < 2; c++) {
        __syncthreads();
        for (int it = tid; it < 512; it += 256) {
            int nl = it >> 3, f4 = it & 7;
            int node = nbase + nl;
            int kg = c * 32 + f4 * 4;
            float4 xv = make_float4(0.f, 0.f, 0.f, 0.f);
            if (node < n) xv = __ldg((const float4*)(x + node * 64 + kg));
            int sb = nl * 33 + f4 * 4;
            bufA[sb + 0] = xv.x; bufA[sb + 1] = xv.y;
            bufA[sb + 2] = xv.z; bufA[sb + 3] = xv.w;
        }
        __syncthreads();
        const float* wm = swx + c * 32 * 64;
#pragma unroll 8
        for (int k = 0; k < 32; k++) {
            float a[4];
#pragma unroll
            for (int i = 0; i < 4; i++) a[i] = bufA[(tm * 4 + i) * 33 + k];
            float4 wv = *(const float4*)(wm + k * 64 + tn * 4);
#pragma unroll
            for (int i = 0; i < 4; i++) {
                accM[i][0] += a[i] * wv.x; accM[i][1] += a[i] * wv.y;
                accM[i][2] += a[i] * wv.z; accM[i][3] += a[i] * wv.w;
            }
        }
    }

    float e0 = __expf(lam1[0]), e1 = __expf(lam1[1]);
    float lamxl = e0 / (e0 + e1), laml = e1 / (e0 + e1);
    float f0 = __expf(lam2[0]), f1 = __expf(lam2[1]);
    float lamxh = f0 / (f0 + f1), lamh = f1 / (f0 + f1);

    __syncthreads();   // done reading bufA/bufB; reuse as xf stage
#pragma unroll
    for (int i = 0; i < 4; i++) {
        int node = nbase + tm * 4 + i;
        float lamx = (node < n && __ldg(cc + node)) ? lamxl : lamxh;
        float* st = sxf + (tm * 4 + i) * 65 + tn * 4;
        st[0] = fmaxf(lamx * accM[i][0] + laml * accZ2[i][0] + lamh * accZ4[i][0], 0.f);
        st[1] = fmaxf(lamx * accM[i][1] + laml * accZ2[i][1] + lamh * accZ4[i][1], 0.f);
        st[2] = fmaxf(lamx * accM[i][2] + laml * accZ2[i][2] + lamh * accZ4[i][2], 0.f);
        st[3] = fmaxf(lamx * accM[i][3] + laml * accZ2[i][3] + lamh * accZ4[i][3], 0.f);
    }
    __syncthreads();

    // ---- fused classifier: out[node] = xf[node] @ linW + linB ----
    int nl2 = tid >> 2;            // 0..63
    int og  = (tid & 3) * 10;      // 0,10,20,30
    int node = nbase + nl2;
    if (node < n) {
        float accv[10];
#pragma unroll
        for (int j = 0; j < 10; j++) accv[j] = slinb[og + j];
        const float* xr = sxf + nl2 * 65;
#pragma unroll 8
        for (int k = 0; k < 64; k++) {
            float b = xr[k];
            const float* wr = slin + k * 40 + og;
#pragma unroll
            for (int j = 0; j < 10; j++) accv[j] += b * wr[j];
        }
#pragma unroll
        for (int j = 0; j < 10; j++) out[node * 40 + og + j] = accv[j];
    }
}

// ---------------- host launcher --------------------------------------------
extern "C" void kernel_launch(void* const* d_in, const int* in_sizes, int n_in,
                              void* d_out, int out_size) {
    const float* x    = (const float*)d_in[0];
    const int*   ei   = (const int*)d_in[1];
    const int*   cc   = (const int*)d_in[2];
    const float* W1l  = (const float*)d_in[3];
    const float* W1r  = (const float*)d_in[4];
    const float* W2l  = (const float*)d_in[5];
    const float* W2r  = (const float*)d_in[6];
    const float* W3l  = (const float*)d_in[7];
    const float* W3r  = (const float*)d_in[8];
    const float* W4l  = (const float*)d_in[9];
    const float* W4r  = (const float*)d_in[10];
    const float* WX   = (const float*)d_in[11];
    const float* lam1 = (const float*)d_in[12];
    const float* lam2 = (const float*)d_in[13];
    const float* linW = (const float*)d_in[14];
    const float* linB = (const float*)d_in[15];
    float* out = (float*)d_out;

    int n = in_sizes[0] / 64;
    int E = in_sizes[1] / 2;
    const int* col = ei;
    const int* row = ei + E;
    int nblk = (n + 1023) / 1024;

    cudaFuncSetAttribute(k_dense1, cudaFuncAttributeMaxDynamicSharedMemorySize,
                         D1_SMEM_FLOATS * 4);
    cudaFuncSetAttribute(k_dense2, cudaFuncAttributeMaxDynamicSharedMemorySize,
                         D2_SMEM_FLOATS * 4);

    k_zero_small<<<(n + 255) / 256, 256>>>(n);
    k_deg<<<(E + 255) / 256, 256>>>(col, row, cc, E);
    k_scanA<<<nblk, 1024>>>(n);
    k_scanB<<<1, 128>>>(nblk);
    k_scanC<<<nblk, 1024>>>(cc, n);
    k_scatter<<<(E + 255) / 256, 256>>>(col, row, cc, E);
    k_gather0<<<(n + 7) / 8, 256>>>(cc, x, n);
    k_dense1<<<(n + 127) / 128, 256, D1_SMEM_FLOATS * 4>>>(x, W1l, W1r, W3l, W3r, n);
    k_gather1<<<(n + 7) / 8, 256>>>(n);
    k_dense2<<<(n + 63) / 64, 256, D2_SMEM_FLOATS * 4>>>(x, cc, W2l, W2r, W4l, W4r,
                                                         WX, lam1, lam2, linW, linB,
                                                         out, n);
}

// round 5
// speedup vs baseline: 2.3775x; 1.0204x over previous
#include <cuda_runtime.h>

#define NMAX 100000
#define EMAX 1600000

typedef unsigned long long u64;

// ---------------- packed f32x2 helpers (Blackwell FFMA2) --------------------
__device__ __forceinline__ u64 ffma2(u64 a, u64 b, u64 c) {
    u64 d;
    asm("fma.rn.f32x2 %0, %1, %2, %3;" : "=l"(d) : "l"(a), "l"(b), "l"(c));
    return d;
}
__device__ __forceinline__ u64 bcast2(float a) {
    u64 r;
    asm("mov.b64 %0, {%1, %1};" : "=l"(r) : "f"(a));
    return r;
}
__device__ __forceinline__ u64 pack2f(float lo, float hi) {
    u64 r;
    asm("mov.b64 %0, {%1, %2};" : "=l"(r) : "f"(lo), "f"(hi));
    return r;
}
__device__ __forceinline__ float2 unpack2(u64 v) {
    float lo, hi;
    asm("mov.b64 {%0, %1}, %2;" : "=f"(lo), "=f"(hi) : "l"(v));
    return make_float2(lo, hi);
}

// ---------------- scratch (device globals; no allocation allowed) ----------
__device__ float g_y1[NMAX * 64];
__device__ float g_y2[NMAX * 64];
__device__ float g_y3[NMAX * 64];
__device__ float g_y4[NMAX * 64];
__device__ float g_xl[NMAX * 64];
__device__ float g_xh[NMAX * 64];
__device__ float2 g_D1[NMAX];
__device__ float2 g_D2[NMAX];
__device__ int    g_cnt[NMAX];
__device__ int    g_ptr[NMAX];
__device__ int    g_pos[NMAX];
__device__ int    g_adj[EMAX];
__device__ int    g_bsum[128];
__device__ int    g_boff[128];

// ---------------- tiny zero -------------------------------------------------
__global__ void k_zero_small(int n) {
    int i = blockIdx.x * blockDim.x + threadIdx.x;
    if (i < n) g_cnt[i] = 0;
}

// ---------------- degree pass (packed single atomic per edge) ---------------
__global__ void k_deg(const int* __restrict__ col, const int* __restrict__ row,
                      const int* __restrict__ cc, int E) {
    int e = blockIdx.x * blockDim.x + threadIdx.x;
    if (e >= E) return;
    int r = __ldg(row + e);
    int c = __ldg(col + e);
    if (r == c) return;
    atomicAdd(&g_cnt[r], 0x10000 | __ldg(cc + c));
}

// ---------------- scan kernel A ---------------------------------------------
__global__ void k_scanA(int n) {
    __shared__ int sm[1024];
    int tid = threadIdx.x;
    int i = blockIdx.x * 1024 + tid;
    int v = (i < n) ? (g_cnt[i] >> 16) : 0;
    sm[tid] = v;
    __syncthreads();
    for (int off = 512; off; off >>= 1) {
        if (tid < off) sm[tid] += sm[tid + off];
        __syncthreads();
    }
    if (tid == 0) g_bsum[blockIdx.x] = sm[0];
}

// ---------------- scan kernel B ---------------------------------------------
__global__ void k_scanB(int nb) {
    int t = threadIdx.x;
    int lane = t & 31, w = t >> 5;
    int v = (t < nb) ? g_bsum[t] : 0;
    int xv = v;
    const unsigned F = 0xffffffffu;
#pragma unroll
    for (int o = 1; o < 32; o <<= 1) {
        int y = __shfl_up_sync(F, xv, o);
        if (lane >= o) xv += y;
    }
    __shared__ int ws[4];
    if (lane == 31) ws[w] = xv;
    __syncthreads();
    __shared__ int wo[4];
    if (t == 0) {
        int a = 0;
        for (int i = 0; i < 4; i++) { wo[i] = a; a += ws[i]; }
    }
    __syncthreads();
    if (t < 128) g_boff[t] = xv + wo[w] - v;
}

// ---------------- scan kernel C ---------------------------------------------
__global__ void k_scanC(const int* __restrict__ cc, int n) {
    __shared__ int ws[32];
    int tid = threadIdx.x;
    int lane = tid & 31, w = tid >> 5;
    int i = blockIdx.x * 1024 + tid;
    int packed = (i < n) ? g_cnt[i] : 0;
    int v = packed >> 16;
    int xv = v;
    const unsigned F = 0xffffffffu;
#pragma unroll
    for (int o = 1; o < 32; o <<= 1) {
        int y = __shfl_up_sync(F, xv, o);
        if (lane >= o) xv += y;
    }
    if (lane == 31) ws[w] = xv;
    __syncthreads();
    if (w == 0) {
        int t2 = ws[lane];
        int sv = t2;
#pragma unroll
        for (int o = 1; o < 32; o <<= 1) {
            int y = __shfl_up_sync(F, sv, o);
            if (lane >= o) sv += y;
        }
        ws[lane] = sv - t2;
    }
    __syncthreads();
    if (i < n) {
        int ptr = g_boff[blockIdx.x] + ws[w] + xv - v;
        g_ptr[i] = ptr;
        g_pos[i] = ptr;
        g_cnt[i] = v;
        float cnt = (float)v;
        float sv2 = (float)(packed & 0xffff);
        int cci = __ldg(cc + i);
        float dl  = rsqrtf((cci ? cnt : 0.f) + 1.f);
        float dh  = rsqrtf((cci ? 0.f : cnt) + 1.f);
        float dll = rsqrtf(sv2 + 1.f);
        float dhh = rsqrtf(cnt - sv2 + 1.f);
        g_D1[i] = make_float2(dl, dh);
        g_D2[i] = make_float2(dll, dhh);
    }
}

// ---------------- scatter: build adjacency ----------------------------------
__global__ void k_scatter(const int* __restrict__ col, const int* __restrict__ row,
                          const int* __restrict__ cc, int E) {
    int e = blockIdx.x * blockDim.x + threadIdx.x;
    if (e >= E) return;
    int r = __ldg(row + e);
    int c = __ldg(col + e);
    if (r == c) return;
    int p = atomicAdd(&g_pos[r], 1);
    g_adj[p] = (c << 1) | __ldg(cc + c);
}

// ---------------- gather pass 0 ---------------------------------------------
__global__ void __launch_bounds__(256) k_gather0(const int* __restrict__ cc,
                                                 const float* __restrict__ x,
                                                 int n) {
    int tid = threadIdx.x;
    int warp = tid >> 5, l = tid & 31;
    int r = blockIdx.x * 8 + warp;
    if (r >= n) return;
    int half = l >> 4, q = l & 15;

    int ccr = __ldg(cc + r);
    float2 d1r = g_D1[r];
    float drv = ccr ? d1r.x : d1r.y;
    int start = g_ptr[r];
    int deg = g_cnt[r];

    u64 acc0 = 0ull, acc1 = 0ull;
    const unsigned F = 0xffffffffu;
    for (int j0 = 0; j0 < deg; j0 += 32) {
        int myp = 0;
        if (j0 + l < deg) myp = __ldg(g_adj + start + j0 + l);
        int kmax = deg - j0; if (kmax > 32) kmax = 32;
        int pairs = (kmax + 1) >> 1;
        for (int k = 0; k < pairs; k++) {
            int idx = 2 * k + half;
            int packed = __shfl_sync(F, myp, idx);
            int c = packed >> 1;
            float2 d1c = __ldg(&g_D1[c]);
            float w = drv * (ccr ? d1c.x : d1c.y);
            if (idx >= kmax) w = 0.f;
            u64 wp = bcast2(w);
            ulonglong2 v = __ldg((const ulonglong2*)(x + c * 64) + q);
            acc0 = ffma2(wp, v.x, acc0);
            acc1 = ffma2(wp, v.y, acc1);
        }
    }
    float2 p0 = unpack2(acc0), p1 = unpack2(acc1);
    p0.x += __shfl_xor_sync(F, p0.x, 16);
    p0.y += __shfl_xor_sync(F, p0.y, 16);
    p1.x += __shfl_xor_sync(F, p1.x, 16);
    p1.y += __shfl_xor_sync(F, p1.y, 16);
    if (half == 0) {
        float4 acc = make_float4(p0.x, p0.y, p1.x, p1.y);
        float4 z = make_float4(0.f, 0.f, 0.f, 0.f);
        float4* y1 = (float4*)(g_y1 + r * 64) + q;
        float4* y3 = (float4*)(g_y3 + r * 64) + q;
        if (ccr) { *y1 = acc; *y3 = z; }
        else     { *y3 = acc; *y1 = z; }
    }
}

// ---------------- gather pass 1 ---------------------------------------------
__global__ void __launch_bounds__(256) k_gather1(int n) {
    int tid = threadIdx.x;
    int warp = tid >> 5, l = tid & 31;
    int r = blockIdx.x * 8 + warp;
    if (r >= n) return;
    int half = l >> 4, q = l & 15;

    float2 d2r = g_D2[r];
    float dllr = d2r.x, dhhr = d2r.y;
    int start = g_ptr[r];
    int deg = g_cnt[r];

    u64 a20 = 0ull, a21 = 0ull, a40 = 0ull, a41 = 0ull;
    const unsigned F = 0xffffffffu;
    for (int j0 = 0; j0 < deg; j0 += 32) {
        int myp = 0;
        if (j0 + l < deg) myp = __ldg(g_adj + start + j0 + l);
        int kmax = deg - j0; if (kmax > 32) kmax = 32;
        int pairs = (kmax + 1) >> 1;
        for (int k = 0; k < pairs; k++) {
            int idx = 2 * k + half;
            int packed = __shfl_sync(F, myp, idx);
            int c = packed >> 1;
            int sel = packed & 1;
            float2 d2c = __ldg(&g_D2[c]);
            float w2 = sel ? dllr * d2c.x : 0.f;
            float w4 = sel ? 0.f : dhhr * d2c.y;
            if (idx >= kmax) { w2 = 0.f; w4 = 0.f; }
            const float* src = sel ? g_xl : g_xh;
            ulonglong2 v = __ldg((const ulonglong2*)(src + c * 64) + q);
            u64 w2p = bcast2(w2), w4p = bcast2(w4);
            a20 = ffma2(w2p, v.x, a20);
            a21 = ffma2(w2p, v.y, a21);
            a40 = ffma2(w4p, v.x, a40);
            a41 = ffma2(w4p, v.y, a41);
        }
    }
    float2 q20 = unpack2(a20), q21 = unpack2(a21);
    float2 q40 = unpack2(a40), q41 = unpack2(a41);
    q20.x += __shfl_xor_sync(F, q20.x, 16);
    q20.y += __shfl_xor_sync(F, q20.y, 16);
    q21.x += __shfl_xor_sync(F, q21.x, 16);
    q21.y += __shfl_xor_sync(F, q21.y, 16);
    q40.x += __shfl_xor_sync(F, q40.x, 16);
    q40.y += __shfl_xor_sync(F, q40.y, 16);
    q41.x += __shfl_xor_sync(F, q41.x, 16);
    q41.y += __shfl_xor_sync(F, q41.y, 16);
    if (half == 0) {
        *((float4*)(g_y2 + r * 64) + q) = make_float4(q20.x, q20.y, q21.x, q21.y);
        *((float4*)(g_y4 + r * 64) + q) = make_float4(q40.x, q40.y, q41.x, q41.y);
    }
}

// ---------------- dense layer 1 (FFMA2 register-tiled GEMM) -----------------
#define D1_SMEM_FLOATS (4 * 4096 + 2 * 128 * 33)
__global__ void __launch_bounds__(256, 2) k_dense1(const float* __restrict__ x,
                                                   const float* __restrict__ W1l,
                                                   const float* __restrict__ W1r,
                                                   const float* __restrict__ W3l,
                                                   const float* __restrict__ W3r,
                                                   int n) {
    extern __shared__ float s[];
    float* sw1l = s;
    float* sw1r = s + 4096;
    float* sw3l = s + 8192;
    float* sw3r = s + 12288;
    float* bufA = s + 16384;
    float* bufB = s + 16384 + 128 * 33;

    int tid = threadIdx.x;
    {
        float4* d4 = (float4*)s;
        for (int i = tid; i < 4096; i += 256) {
            const float* srcm = (i < 1024) ? W1l : (i < 2048) ? W1r : (i < 3072) ? W3l : W3r;
            d4[i] = ((const float4*)srcm)[i & 1023];
        }
    }

    int tn = tid & 7;
    int tm = tid >> 3;
    int nbase = blockIdx.x * 128;

    u64 accL[4][4], accH[4][4];
#pragma unroll
    for (int i = 0; i < 4; i++)
#pragma unroll
        for (int j = 0; j < 4; j++) { accL[i][j] = 0ull; accH[i][j] = 0ull; }

    for (int c = 0; c < 2; c++) {
        __syncthreads();
        for (int it = tid; it < 1024; it += 256) {
            int nl = it >> 3, f4 = it & 7;
            int node = nbase + nl;
            int kg = c * 32 + f4 * 4;
            float4 xv = make_float4(0.f, 0.f, 0.f, 0.f), y1v = xv, y3v = xv;
            float dl2 = 0.f, dh2 = 0.f;
            if (node < n) {
                xv  = __ldg((const float4*)(x + node * 64 + kg));
                y1v = *((const float4*)(g_y1 + node * 64 + kg));
                y3v = *((const float4*)(g_y3 + node * 64 + kg));
                float2 d = g_D1[node];
                dl2 = d.x * d.x; dh2 = d.y * d.y;
            }
            int sb = nl * 33 + f4 * 4;
            bufA[sb + 0] = y1v.x + dl2 * xv.x;
            bufA[sb + 1] = y1v.y + dl2 * xv.y;
            bufA[sb + 2] = y1v.z + dl2 * xv.z;
            bufA[sb + 3] = y1v.w + dl2 * xv.w;
            bufB[sb + 0] = y3v.x + dh2 * xv.x;
            bufB[sb + 1] = y3v.y + dh2 * xv.y;
            bufB[sb + 2] = y3v.z + dh2 * xv.z;
            bufB[sb + 3] = y3v.w + dh2 * xv.w;
        }
        __syncthreads();
        const float* wl = sw1l + c * 32 * 64;
        const float* wh = sw3l + c * 32 * 64;
#pragma unroll 8
        for (int k = 0; k < 32; k++) {
            u64 a1p[4], a3p[4];
#pragma unroll
            for (int i = 0; i < 4; i++) {
                a1p[i] = bcast2(bufA[(tm * 4 + i) * 33 + k]);
                a3p[i] = bcast2(bufB[(tm * 4 + i) * 33 + k]);
            }
            ulonglong2 l0 = *(const ulonglong2*)(wl + k * 64 + tn * 8);
            ulonglong2 l1 = *(const ulonglong2*)(wl + k * 64 + tn * 8 + 4);
            ulonglong2 h0 = *(const ulonglong2*)(wh + k * 64 + tn * 8);
            ulonglong2 h1 = *(const ulonglong2*)(wh + k * 64 + tn * 8 + 4);
#pragma unroll
            for (int i = 0; i < 4; i++) {
                accL[i][0] = ffma2(a1p[i], l0.x, accL[i][0]);
                accL[i][1] = ffma2(a1p[i], l0.y, accL[i][1]);
                accL[i][2] = ffma2(a1p[i], l1.x, accL[i][2]);
                accL[i][3] = ffma2(a1p[i], l1.y, accL[i][3]);
                accH[i][0] = ffma2(a3p[i], h0.x, accH[i][0]);
                accH[i][1] = ffma2(a3p[i], h0.y, accH[i][1]);
                accH[i][2] = ffma2(a3p[i], h1.x, accH[i][2]);
                accH[i][3] = ffma2(a3p[i], h1.y, accH[i][3]);
            }
        }
    }

    for (int c = 0; c < 2; c++) {
        __syncthreads();
        for (int it = tid; it < 1024; it += 256) {
            int nl = it >> 3, f4 = it & 7;
            int node = nbase + nl;
            int kg = c * 32 + f4 * 4;
            float4 xv = make_float4(0.f, 0.f, 0.f, 0.f);
            if (node < n) xv = __ldg((const float4*)(x + node * 64 + kg));
            int sb = nl * 33 + f4 * 4;
            bufA[sb + 0] = xv.x; bufA[sb + 1] = xv.y;
            bufA[sb + 2] = xv.z; bufA[sb + 3] = xv.w;
        }
        __syncthreads();
        const float* wl = sw1r + c * 32 * 64;
        const float* wh = sw3r + c * 32 * 64;
#pragma unroll 8
        for (int k = 0; k < 32; k++) {
            u64 ap[4];
#pragma unroll
            for (int i = 0; i < 4; i++) ap[i] = bcast2(bufA[(tm * 4 + i) * 33 + k]);
            ulonglong2 l0 = *(const ulonglong2*)(wl + k * 64 + tn * 8);
            ulonglong2 l1 = *(const ulonglong2*)(wl + k * 64 + tn * 8 + 4);
            ulonglong2 h0 = *(const ulonglong2*)(wh + k * 64 + tn * 8);
            ulonglong2 h1 = *(const ulonglong2*)(wh + k * 64 + tn * 8 + 4);
#pragma unroll
            for (int i = 0; i < 4; i++) {
                accL[i][0] = ffma2(ap[i], l0.x, accL[i][0]);
                accL[i][1] = ffma2(ap[i], l0.y, accL[i][1]);
                accL[i][2] = ffma2(ap[i], l1.x, accL[i][2]);
                accL[i][3] = ffma2(ap[i], l1.y, accL[i][3]);
                accH[i][0] = ffma2(ap[i], h0.x, accH[i][0]);
                accH[i][1] = ffma2(ap[i], h0.y, accH[i][1]);
                accH[i][2] = ffma2(ap[i], h1.x, accH[i][2]);
                accH[i][3] = ffma2(ap[i], h1.y, accH[i][3]);
            }
        }
    }

#pragma unroll
    for (int i = 0; i < 4; i++) {
        int node = nbase + tm * 4 + i;
        if (node >= n) continue;
        float2 p0 = unpack2(accL[i][0]), p1 = unpack2(accL[i][1]);
        float2 p2 = unpack2(accL[i][2]), p3 = unpack2(accL[i][3]);
        float4 v0 = make_float4(fmaxf(p0.x, 0.f), fmaxf(p0.y, 0.f),
                                fmaxf(p1.x, 0.f), fmaxf(p1.y, 0.f));
        float4 v1 = make_float4(fmaxf(p2.x, 0.f), fmaxf(p2.y, 0.f),
                                fmaxf(p3.x, 0.f), fmaxf(p3.y, 0.f));
        *((float4*)(g_xl + node * 64 + tn * 8))     = v0;
        *((float4*)(g_xl + node * 64 + tn * 8 + 4)) = v1;
        p0 = unpack2(accH[i][0]); p1 = unpack2(accH[i][1]);
        p2 = unpack2(accH[i][2]); p3 = unpack2(accH[i][3]);
        v0 = make_float4(fmaxf(p0.x, 0.f), fmaxf(p0.y, 0.f),
                         fmaxf(p1.x, 0.f), fmaxf(p1.y, 0.f));
        v1 = make_float4(fmaxf(p2.x, 0.f), fmaxf(p2.y, 0.f),
                         fmaxf(p3.x, 0.f), fmaxf(p3.y, 0.f));
        *((float4*)(g_xh + node * 64 + tn * 8))     = v0;
        *((float4*)(g_xh + node * 64 + tn * 8 + 4)) = v1;
    }
}

// ---------------- dense layer 2 GEMM + mix + FUSED classifier ---------------
#define D2_SMEM_FLOATS (5 * 4096 + 2 * 64 * 33 + 2560 + 40)
__global__ void __launch_bounds__(256, 2) k_dense2(const float* __restrict__ x,
                                                   const int* __restrict__ cc,
                                                   const float* __restrict__ W2l,
                                                   const float* __restrict__ W2r,
                                                   const float* __restrict__ W4l,
                                                   const float* __restrict__ W4r,
                                                   const float* __restrict__ WX,
                                                   const float* __restrict__ lam1,
                                                   const float* __restrict__ lam2,
                                                   const float* __restrict__ linW,
                                                   const float* __restrict__ linB,
                                                   float* __restrict__ out, int n) {
    extern __shared__ float s[];
    float* sw2l = s;
    float* sw2r = s + 4096;
    float* sw4l = s + 8192;
    float* sw4r = s + 12288;
    float* swx  = s + 16384;
    float* bufA = s + 20480;
    float* bufB = s + 20480 + 64 * 33;
    float* sxf  = bufA;                 // reused: 64 nodes x 65 stride
    float* slin  = s + 24704;
    float* slinb = s + 27264;

    int tid = threadIdx.x;
    {
        float4* d4 = (float4*)s;
        for (int i = tid; i < 5120; i += 256) {
            const float* srcm = (i < 1024) ? W2l : (i < 2048) ? W2r :
                                (i < 3072) ? W4l : (i < 4096) ? W4r : WX;
            d4[i] = ((const float4*)srcm)[i & 1023];
        }
        float4* l4 = (float4*)slin;
        for (int i = tid; i < 640; i += 256) l4[i] = ((const float4*)linW)[i];
        if (tid < 40) slinb[tid] = linB[tid];
    }

    int tn = tid & 15;
    int tm = tid >> 4;
    int nbase = blockIdx.x * 64;

    u64 accZ2[4][2], accZ4[4][2], accM[4][2];
#pragma unroll
    for (int i = 0; i < 4; i++)
#pragma unroll
        for (int j = 0; j < 2; j++) { accZ2[i][j] = 0ull; accZ4[i][j] = 0ull; accM[i][j] = 0ull; }

    for (int c = 0; c < 2; c++) {
        __syncthreads();
        for (int it = tid; it < 512; it += 256) {
            int nl = it >> 3, f4 = it & 7;
            int node = nbase + nl;
            int kg = c * 32 + f4 * 4;
            float4 xlv = make_float4(0.f, 0.f, 0.f, 0.f), xhv = xlv, y2v = xlv, y4v = xlv;
            float dll2 = 0.f, dhh2 = 0.f;
            if (node < n) {
                xlv = *((const float4*)(g_xl + node * 64 + kg));
                xhv = *((const float4*)(g_xh + node * 64 + kg));
                y2v = *((const float4*)(g_y2 + node * 64 + kg));
                y4v = *((const float4*)(g_y4 + node * 64 + kg));
                float2 d = g_D2[node];
                dll2 = d.x * d.x; dhh2 = d.y * d.y;
            }
            int sb = nl * 33 + f4 * 4;
            bufA[sb + 0] = y2v.x + dll2 * xlv.x;
            bufA[sb + 1] = y2v.y + dll2 * xlv.y;
            bufA[sb + 2] = y2v.z + dll2 * xlv.z;
            bufA[sb + 3] = y2v.w + dll2 * xlv.w;
            bufB[sb + 0] = y4v.x + dhh2 * xhv.x;
            bufB[sb + 1] = y4v.y + dhh2 * xhv.y;
            bufB[sb + 2] = y4v.z + dhh2 * xhv.z;
            bufB[sb + 3] = y4v.w + dhh2 * xhv.w;
        }
        __syncthreads();
        const float* w2 = sw2l + c * 32 * 64;
        const float* w4 = sw4l + c * 32 * 64;
#pragma unroll 8
        for (int k = 0; k < 32; k++) {
            u64 a2p[4], a4p[4];
#pragma unroll
            for (int i = 0; i < 4; i++) {
                a2p[i] = bcast2(bufA[(tm * 4 + i) * 33 + k]);
                a4p[i] = bcast2(bufB[(tm * 4 + i) * 33 + k]);
            }
            ulonglong2 wz2 = *(const ulonglong2*)(w2 + k * 64 + tn * 4);
            ulonglong2 wz4 = *(const ulonglong2*)(w4 + k * 64 + tn * 4);
#pragma unroll
            for (int i = 0; i < 4; i++) {
                accZ2[i][0] = ffma2(a2p[i], wz2.x, accZ2[i][0]);
                accZ2[i][1] = ffma2(a2p[i], wz2.y, accZ2[i][1]);
                accZ4[i][0] = ffma2(a4p[i], wz4.x, accZ4[i][0]);
                accZ4[i][1] = ffma2(a4p[i], wz4.y, accZ4[i][1]);
            }
        }
    }

    for (int c = 0; c < 2; c++) {
        __syncthreads();
        for (int it = tid; it < 512; it += 256) {
            int nl = it >> 3, f4 = it & 7;
            int node = nbase + nl;
            int kg = c * 32 + f4 * 4;
            float4 xlv = make_float4(0.f, 0.f, 0.f, 0.f), xhv = xlv;
            if (node < n) {
                xlv = *((const float4*)(g_xl + node * 64 + kg));
                xhv = *((const float4*)(g_xh + node * 64 + kg));
            }
            int sb = nl * 33 + f4 * 4;
            bufA[sb + 0] = xlv.x; bufA[sb + 1] = xlv.y;
            bufA[sb + 2] = xlv.z; bufA[sb + 3] = xlv.w;
            bufB[sb + 0] = xhv.x; bufB[sb + 1] = xhv.y;
            bufB[sb + 2] = xhv.z; bufB[sb + 3] = xhv.w;
        }
        __syncthreads();
        const float* w2 = sw2r + c * 32 * 64;
        const float* w4 = sw4r + c * 32 * 64;
#pragma unroll 8
        for (int k = 0; k < 32; k++) {
            u64 a2p[4], a4p[4];
#pragma unroll
            for (int i = 0; i < 4; i++) {
                a2p[i] = bcast2(bufA[(tm * 4 + i) * 33 + k]);
                a4p[i] = bcast2(bufB[(tm * 4 + i) * 33 + k]);
            }
            ulonglong2 wz2 = *(const ulonglong2*)(w2 + k * 64 + tn * 4);
            ulonglong2 wz4 = *(const ulonglong2*)(w4 + k * 64 + tn * 4);
#pragma unroll
            for (int i = 0; i < 4; i++) {
                accZ2[i][0] = ffma2(a2p[i], wz2.x, accZ2[i][0]);
                accZ2[i][1] = ffma2(a2p[i], wz2.y, accZ2[i][1]);
                accZ4[i][0] = ffma2(a4p[i], wz4.x, accZ4[i][0]);
                accZ4[i][1] = ffma2(a4p[i], wz4.y, accZ4[i][1]);
            }
        }
    }

    for (int c = 0; c < 2; c++) {
        __syncthreads();
        for (int it = tid; it < 512; it += 256) {
            int nl = it >> 3, f4 = it & 7;
            int node = nbase + nl;
            int kg = c * 32 + f4 * 4;
            float4 xv = make_float4(0.f, 0.f, 0.f, 0.f);
            if (node < n) xv = __ldg((const float4*)(x + node * 64 + kg));
            int sb = nl * 33 + f4 * 4;
            bufA[sb + 0] = xv.x; bufA[sb + 1] = xv.y;
            bufA[sb + 2] = xv.z; bufA[sb + 3] = xv.w;
        }
        __syncthreads();
        const float* wm = swx + c * 32 * 64;
#pragma unroll 8
        for (int k = 0; k < 32; k++) {
            u64 ap[4];
#pragma unroll
            for (int i = 0; i < 4; i++) ap[i] = bcast2(bufA[(tm * 4 + i) * 33 + k]);
            ulonglong2 wv = *(const ulonglong2*)(wm + k * 64 + tn * 4);
#pragma unroll
            for (int i = 0; i < 4; i++) {
                accM[i][0] = ffma2(ap[i], wv.x, accM[i][0]);
                accM[i][1] = ffma2(ap[i], wv.y, accM[i][1]);
            }
        }
    }

    float e0 = __expf(lam1[0]), e1 = __expf(lam1[1]);
    float lamxl = e0 / (e0 + e1), laml = e1 / (e0 + e1);
    float f0 = __expf(lam2[0]), f1 = __expf(lam2[1]);
    float lamxh = f0 / (f0 + f1), lamh = f1 / (f0 + f1);

    __syncthreads();   // done reading bufA/bufB; reuse as xf stage
#pragma unroll
    for (int i = 0; i < 4; i++) {
        int node = nbase + tm * 4 + i;
        float lamx = (node < n && __ldg(cc + node)) ? lamxl : lamxh;
        float* st = sxf + (tm * 4 + i) * 65 + tn * 4;
#pragma unroll
        for (int j = 0; j < 2; j++) {
            float2 m = unpack2(accM[i][j]);
            float2 z2 = unpack2(accZ2[i][j]);
            float2 z4 = unpack2(accZ4[i][j]);
            st[2 * j + 0] = fmaxf(lamx * m.x + laml * z2.x + lamh * z4.x, 0.f);
            st[2 * j + 1] = fmaxf(lamx * m.y + laml * z2.y + lamh * z4.y, 0.f);
        }
    }
    __syncthreads();

    // ---- fused classifier: out[node] = xf[node] @ linW + linB (FFMA2) ----
    int nl2 = tid >> 2;            // 0..63
    int og  = (tid & 3) * 10;      // 0,10,20,30
    int node = nbase + nl2;
    if (node < n) {
        u64 accv[5];
#pragma unroll
        for (int j = 0; j < 5; j++) accv[j] = pack2f(slinb[og + 2 * j], slinb[og + 2 * j + 1]);
        const float* xr = sxf + nl2 * 65;
#pragma unroll 8
        for (int k = 0; k < 64; k++) {
            u64 bp = bcast2(xr[k]);
            const u64* wr = (const u64*)(slin + k * 40 + og);
#pragma unroll
            for (int j = 0; j < 5; j++) accv[j] = ffma2(bp, wr[j], accv[j]);
        }
#pragma unroll
        for (int j = 0; j < 5; j++) {
            float2 p = unpack2(accv[j]);
            out[node * 40 + og + 2 * j]     = p.x;
            out[node * 40 + og + 2 * j + 1] = p.y;
        }
    }
}

// ---------------- host launcher --------------------------------------------
extern "C" void kernel_launch(void* const* d_in, const int* in_sizes, int n_in,
                              void* d_out, int out_size) {
    const float* x    = (const float*)d_in[0];
    const int*   ei   = (const int*)d_in[1];
    const int*   cc   = (const int*)d_in[2];
    const float* W1l  = (const float*)d_in[3];
    const float* W1r  = (const float*)d_in[4];
    const float* W2l  = (const float*)d_in[5];
    const float* W2r  = (const float*)d_in[6];
    const float* W3l  = (const float*)d_in[7];
    const float* W3r  = (const float*)d_in[8];
    const float* W4l  = (const float*)d_in[9];
    const float* W4r  = (const float*)d_in[10];
    const float* WX   = (const float*)d_in[11];
    const float* lam1 = (const float*)d_in[12];
    const float* lam2 = (const float*)d_in[13];
    const float* linW = (const float*)d_in[14];
    const float* linB = (const float*)d_in[15];
    float* out = (float*)d_out;

    int n = in_sizes[0] / 64;
    int E = in_sizes[1] / 2;
    const int* col = ei;
    const int* row = ei + E;
    int nblk = (n + 1023) / 1024;

    cudaFuncSetAttribute(k_dense1, cudaFuncAttributeMaxDynamicSharedMemorySize,
                         D1_SMEM_FLOATS * 4);
    cudaFuncSetAttribute(k_dense2, cudaFuncAttributeMaxDynamicSharedMemorySize,
                         D2_SMEM_FLOATS * 4);

    k_zero_small<<<(n + 255) / 256, 256>>>(n);
    k_deg<<<(E + 255) / 256, 256>>>(col, row, cc, E);
    k_scanA<<<nblk, 1024>>>(n);
    k_scanB<<<1, 128>>>(nblk);
    k_scanC<<<nblk, 1024>>>(cc, n);
    k_scatter<<<(E + 255) / 256, 256>>>(col, row, cc, E);
    k_gather0<<<(n + 7) / 8, 256>>>(cc, x, n);
    k_dense1<<<(n + 127) / 128, 256, D1_SMEM_FLOATS * 4>>>(x, W1l, W1r, W3l, W3r, n);
    k_gather1<<<(n + 7) / 8, 256>>>(n);
    k_dense2<<<(n + 63) / 64, 256, D2_SMEM_FLOATS * 4>>>(x, cc, W2l, W2r, W4l, W4r,
                                                         WX, lam1, lam2, linW, linB,
                                                         out, n);
}